// round 11
// baseline (speedup 1.0000x reference)
#include <cuda_runtime.h>
#include <cuda_bf16.h>
#include <cuda_fp16.h>
#include <cstdint>
#include <cstddef>

// Problem constants
#define BB   4
#define NBL  256
#define LQ   64
#define KK_  65
#define CC   512
#define HH   8
#define SCALE 0.125f
#define THREE_C 1536

// ---------------- scratch (static device globals: allocation-free) ----------------
__device__ __align__(128) __half g_xh[(size_t)BB * NBL * LQ * CC];     // 67MB
__device__ __align__(128) __half g_xl[(size_t)BB * NBL * LQ * CC];     // 67MB
__device__ __align__(128) __half g_bmh[(size_t)BB * NBL * CC];
__device__ __align__(128) __half g_bml[(size_t)BB * NBL * CC];
__device__ __align__(128) __half g_wqh[(size_t)CC * THREE_C];          // [K=512][1536] hi only
__device__ __align__(128) __half g_wph[(size_t)CC * CC];               // [512][512] hi only
__device__ __align__(128) float  g_Q [(size_t)BB * NBL * LQ * CC];     // 134MB
__device__ __align__(128) float  g_KV[(size_t)BB * NBL * KK_ * 2 * CC];// 272MB
__device__ __align__(128) __half g_Oh[(size_t)BB * NBL * LQ * CC];     // 67MB
__device__ __align__(128) __half g_Ol[(size_t)BB * NBL * LQ * CC];     // 67MB
__device__ int g_mask_mode;

// ================= PTX helpers (all baseline compute_80-era, no 'a' features) ===
__device__ __forceinline__ uint32_t smem_u32(const void* p) {
    uint32_t a;
    asm("{ .reg .u64 t; cvta.to.shared.u64 t, %1; cvt.u32.u64 %0, t; }" : "=r"(a) : "l"(p));
    return a;
}
#define CP16(d, s)   asm volatile("cp.async.cg.shared.global [%0], [%1], 16;" :: "r"(d), "l"(s))
#define CP_COMMIT()  asm volatile("cp.async.commit_group;" ::: "memory")
#define CP_WAIT1()   asm volatile("cp.async.wait_group 1;" ::: "memory")

#define LDSM4(d, addr)                                                           \
    asm volatile("ldmatrix.sync.aligned.m8n8.x4.shared.b16 {%0,%1,%2,%3}, [%4];" \
        : "=r"((d)[0]), "=r"((d)[1]), "=r"((d)[2]), "=r"((d)[3]) : "r"(addr))
#define LDSM4T(d, addr)                                                          \
    asm volatile("ldmatrix.sync.aligned.m8n8.x4.trans.shared.b16 {%0,%1,%2,%3}, [%4];" \
        : "=r"((d)[0]), "=r"((d)[1]), "=r"((d)[2]), "=r"((d)[3]) : "r"(addr))

#define MMA16816F16(acc, a, b)                                                   \
    asm volatile("mma.sync.aligned.m16n8k16.row.col.f32.f16.f16.f32 "            \
        "{%0,%1,%2,%3}, {%4,%5,%6,%7}, {%8,%9}, {%0,%1,%2,%3};"                  \
        : "+f"((acc)[0]), "+f"((acc)[1]), "+f"((acc)[2]), "+f"((acc)[3])         \
        : "r"((a)[0]), "r"((a)[1]), "r"((a)[2]), "r"((a)[3]),                    \
          "r"((b)[0]), "r"((b)[1]))

// ================= small kernels =================
__global__ void detect_mask_kernel(const unsigned char* __restrict__ m) {
    __shared__ int sA, s0;
    if (threadIdx.x == 0) { sA = 0; s0 = 0; }
    __syncthreads();
    int a = 0, z = 0;
    for (int i = threadIdx.x; i < 4096; i += blockDim.x) {
        int v = m[i];
        if ((i & 3) == 1) a |= v;
        if ((i & 3) == 0) z |= v;
    }
    if (a) atomicOr(&sA, 1);
    if (z) atomicOr(&s0, 1);
    __syncthreads();
    if (threadIdx.x == 0) g_mask_mode = sA ? 0 : (s0 ? 1 : 2);
}

// block mean -> fp16 hi/lo directly
__global__ void block_mean_kernel(const float* __restrict__ x,
                                  __half* __restrict__ bmh, __half* __restrict__ bml) {
    int blk = blockIdx.x, c = threadIdx.x;
    const float* base = x + (size_t)blk * LQ * CC + c;
    float s = 0.f;
#pragma unroll
    for (int l = 0; l < LQ; l++) s += base[(size_t)l * CC];
    float m = s * (1.0f / 64.0f);
    __half h = __float2half(m);
    bmh[(size_t)blk * CC + c] = h;
    bml[(size_t)blk * CC + c] = __float2half(m - __half2float(h));
}

// fp32 -> fp16 hi + fp16 lo
__global__ void split_kernel(const float* __restrict__ src,
                             __half* __restrict__ dh,
                             __half* __restrict__ dl, size_t n) {
    size_t i = (size_t)blockIdx.x * blockDim.x + threadIdx.x;
    if (i >= n) return;
    float v = src[i];
    __half h = __float2half(v);
    dh[i] = h;
    dl[i] = __float2half(v - __half2float(h));
}

// both weight matrices -> fp16 hi, one launch
__global__ void cvt_weights_kernel(const float* __restrict__ wq,
                                   const float* __restrict__ wp,
                                   __half* __restrict__ wqh, __half* __restrict__ wph) {
    size_t i = (size_t)blockIdx.x * blockDim.x + threadIdx.x;
    const size_t n1 = (size_t)CC * THREE_C;           // 786432
    const size_t n2 = (size_t)CC * CC;                // 262144
    if (i < n1) wqh[i] = __float2half(wq[i]);
    else if (i < n1 + n2) wph[i - n1] = __float2half(wp[i - n1]);
}

// ================= mma.sync fp16 GEMM (2-product compensation) =================
// epi_mode 0: C[M,N] + bias -> C (ldc)
// epi_mode 1: merged QKV: col<512 -> Q (skip kk==64 rows), col>=512 -> KV
// CTA 128x128, 8 warps (2m x 4n). K=512 in 16 chunks of 32; 3-stage cp.async,
// single __syncthreads per chunk (load-ahead distance 2).
#define KCHUNK     32
#define NCHUNK     16
#define A_STRIDE_B 80
#define B_STRIDE_B 272
#define A_HALF     10240                  // 128 * 80
#define B_OFF      20480                  // 2 * A_HALF
#define STAGE_BYTES 29184                 // 2*A_HALF + 32*272
#define GEMM_SMEM  (3 * STAGE_BYTES)      // 87552 -> 2 CTAs/SM

__device__ __forceinline__ void a_ptrs(
    const __half* __restrict__ Ah, const __half* __restrict__ Al,
    const __half* __restrict__ bmh, const __half* __restrict__ bml,
    int gmode, int gr,
    const __half*& ph, const __half*& pl)
{
    if (gmode == 0) { size_t o = (size_t)gr * CC; ph = Ah + o; pl = Al + o; return; }
    int b  = gr / (NBL * KK_);
    int t  = gr - b * (NBL * KK_);
    int nb = t / KK_;
    int kk = t - nb * KK_;
    if (kk < LQ) { size_t o = ((size_t)(b * NBL + nb) * LQ + kk) * CC; ph = Ah + o; pl = Al + o; }
    else         { size_t o = (size_t)(b * NBL + nb) * CC;             ph = bmh + o; pl = bml + o; }
}

__global__ __launch_bounds__(256) void gemm_mma(
    const __half* __restrict__ Ah, const __half* __restrict__ Al,
    const __half* __restrict__ bmh, const __half* __restrict__ bml,
    int gmode,
    const __half* __restrict__ Bh, int ldB,
    const float* __restrict__ bias,
    int epi_mode,
    float* __restrict__ C, int ldc,
    float* __restrict__ Qp, float* __restrict__ KVp)
{
    extern __shared__ __align__(128) char smem[];
    const uint32_t sb = smem_u32(smem);
    const int tid = threadIdx.x, wid = tid >> 5, lane = tid & 31;
    const int warp_m = wid >> 2, warp_n = wid & 3;
    const int rowBase = blockIdx.y * 128;
    const int colBase = blockIdx.x * 128;
    const int g = lane >> 3, r = lane & 7;

    float acc[4][4][4];
#pragma unroll
    for (int ma = 0; ma < 4; ma++)
#pragma unroll
        for (int na = 0; na < 4; na++)
#pragma unroll
            for (int q = 0; q < 4; q++) acc[ma][na][q] = 0.f;

    const uint32_t aOff = (uint32_t)((warp_m * 64 + (g & 1) * 8 + r) * A_STRIDE_B + (g >> 1) * 16);
    const uint32_t bOff = (uint32_t)(B_OFF + ((g & 1) * 8 + r) * B_STRIDE_B
                                     + (warp_n * 32 + (g >> 1) * 8) * 2);

    auto load_chunk = [&](int k0, uint32_t stBase) {
        // A: 128 rows x 32 fp16 (64B) = 4 x 16B per row, hi & lo
#pragma unroll
        for (int i = tid; i < 512; i += 256) {
            int row = i >> 2, seg = i & 3;
            const __half *ph, *pl;
            a_ptrs(Ah, Al, bmh, bml, gmode, rowBase + row, ph, pl);
            uint32_t da = stBase + row * A_STRIDE_B + seg * 16;
            CP16(da,          ph + k0 + seg * 8);
            CP16(da + A_HALF, pl + k0 + seg * 8);
        }
        // B: 32 rows x 128 fp16 (256B) = 16 x 16B per row, hi only
#pragma unroll
        for (int i = tid; i < 512; i += 256) {
            int row = i >> 4, seg = i & 15;
            size_t off = (size_t)(k0 + row) * ldB + colBase + seg * 8;
            CP16(stBase + B_OFF + row * B_STRIDE_B + seg * 16, Bh + off);
        }
    };

    // prologue: stages 0,1
    load_chunk(0, sb);
    CP_COMMIT();
    load_chunk(KCHUNK, sb + STAGE_BYTES);
    CP_COMMIT();

    for (int c = 0; c < NCHUNK; c++) {
        CP_WAIT1();            // chunk c resident (c+1 may still be in flight)
        __syncthreads();       // all warps done with buffer (c-1)%3, chunk c visible
        if (c + 2 < NCHUNK)    // load chunk c+2 into buffer (c+2)%3 == (c-1)%3
            load_chunk((c + 2) * KCHUNK, sb + ((c + 2) % 3) * STAGE_BYTES);
        CP_COMMIT();

        const uint32_t st = sb + (c % 3) * STAGE_BYTES;
#pragma unroll
        for (int ks = 0; ks < 2; ks++) {
            uint32_t ah[4][4], al[4][4], bh[2][4];
#pragma unroll
            for (int ma = 0; ma < 4; ma++) {
                uint32_t ad = st + aOff + ma * (16 * A_STRIDE_B) + ks * 32;
                LDSM4(ah[ma], ad);
                LDSM4(al[ma], ad + A_HALF);
            }
#pragma unroll
            for (int p = 0; p < 2; p++) {
                uint32_t bd = st + bOff + ks * (16 * B_STRIDE_B) + p * 32;
                LDSM4T(bh[p], bd);
            }
#pragma unroll
            for (int ma = 0; ma < 4; ma++)
#pragma unroll
                for (int na = 0; na < 4; na++) {
                    int p = na >> 1, q = (na & 1) * 2;
                    MMA16816F16(acc[ma][na], ah[ma], bh[p] + q);
                    MMA16816F16(acc[ma][na], al[ma], bh[p] + q);
                }
        }
    }

    // ---- epilogue ----
    if (epi_mode == 0) {
#pragma unroll
        for (int ma = 0; ma < 4; ma++) {
            int gr = rowBase + warp_m * 64 + ma * 16 + (lane >> 2);
#pragma unroll
            for (int na = 0; na < 4; na++) {
                int gc = colBase + warp_n * 32 + na * 8 + 2 * (lane & 3);
                float b0 = bias[gc], b1 = bias[gc + 1];
                float2 v0 = make_float2(acc[ma][na][0] + b0, acc[ma][na][1] + b1);
                float2 v1 = make_float2(acc[ma][na][2] + b0, acc[ma][na][3] + b1);
                *(float2*)&C[(size_t)gr * ldc + gc]       = v0;
                *(float2*)&C[(size_t)(gr + 8) * ldc + gc] = v1;
            }
        }
    } else {
        // merged QKV routing; whole CTA column block is Q (colBase<512) or KV.
        const bool isQ = (colBase < 512);
#pragma unroll
        for (int ma = 0; ma < 4; ma++) {
            int gr0 = rowBase + warp_m * 64 + ma * 16 + (lane >> 2);
#pragma unroll
            for (int rr = 0; rr < 2; rr++) {
                int gr = gr0 + rr * 8;
                int b  = gr / (NBL * KK_);
                int t  = gr - b * (NBL * KK_);
                int nb = t / KK_;
                int kk = t - nb * KK_;
                size_t bn = (size_t)b * NBL + nb;
                float* dst;
                int cshift;
                if (isQ) {
                    if (kk >= LQ) continue;             // block-node row: no Q output
                    dst = Qp + (bn * 64 + kk) * 512;
                    cshift = 0;
                } else {
                    dst = KVp + (bn * 65 + kk) * 1024;
                    cshift = 512;
                }
#pragma unroll
                for (int na = 0; na < 4; na++) {
                    int gc = colBase + warp_n * 32 + na * 8 + 2 * (lane & 3);
                    float b0 = bias[gc], b1 = bias[gc + 1];
                    float2 v = make_float2(acc[ma][na][rr * 2] + b0,
                                           acc[ma][na][rr * 2 + 1] + b1);
                    *(float2*)&dst[gc - cshift] = v;
                }
            }
        }
    }
}

// ================= fused per-(b,nb,h) attention (fp32, outputs fp16 hi/lo) ========
#define ATTN_SMEM_FLOATS (64 * 64 + 65 * 65 + 65 * 65 + 64 * 65)

__global__ __launch_bounds__(256) void attn_kernel(
    const float* __restrict__ Qb, const float* __restrict__ KVb,
    const float* __restrict__ edge, const void* __restrict__ maskp,
    __half* __restrict__ Oh, __half* __restrict__ Ol)
{
    extern __shared__ float sm[];
    float* Qs = sm;
    float* Ks = Qs + 64 * 64;
    float* Vs = Ks + 65 * 65;
    float* S  = Vs + 65 * 65;

    const int h  = blockIdx.x;
    const int nb = blockIdx.y;
    const int b  = blockIdx.z;
    const int tid = threadIdx.x;
    const size_t bn = (size_t)b * NBL + nb;

    for (int idx = tid; idx < 64 * 64; idx += 256) {
        int l = idx >> 6, d = idx & 63;
        Qs[idx] = Qb[(bn * 64 + l) * 512 + h * 64 + d];
    }
    for (int idx = tid; idx < 65 * 64; idx += 256) {
        int kk = idx >> 6, d = idx & 63;
        size_t rb = (bn * 65 + kk) * 1024 + h * 64 + d;
        Ks[kk * 65 + d] = KVb[rb];
        Vs[kk * 65 + d] = KVb[rb + 512];
    }
    __syncthreads();

    const int mode = g_mask_mode;

    for (int idx = tid; idx < 64 * 65; idx += 256) {
        int l  = idx / 65;
        int kk = idx - l * 65;
        const float* q  = Qs + l * 64;
        const float* kp = Ks + kk * 65;
        float s = 0.f;
#pragma unroll
        for (int d = 0; d < 64; d++) s = fmaf(q[d], kp[d], s);
        s *= SCALE;

        float bias;
        if (kk == 64 || kk == l) bias = 1.0f;
        else bias = edge[((((size_t)nb * 64) + l) * 65 + kk) * 4 + 3];
        s += bias;

        size_t mi = ((size_t)nb * 64 + l) * 65 + kk;
        bool ok;
        if (mode == 0)      ok = ((const unsigned char*)maskp)[mi] != 0;
        else if (mode == 1) ok = ((const int*)maskp)[mi] != 0;
        else                ok = ((const float*)maskp)[mi] != 0.0f;

        S[l * 65 + kk] = ok ? s : -1.0e9f;
    }
    __syncthreads();

    const int w = tid >> 5, lane = tid & 31;
    for (int rr = w; rr < 64; rr += 8) {
        float mx = -1.0e30f;
        for (int kk = lane; kk < 65; kk += 32) mx = fmaxf(mx, S[rr * 65 + kk]);
#pragma unroll
        for (int off = 16; off; off >>= 1) mx = fmaxf(mx, __shfl_xor_sync(0xffffffffu, mx, off));
        float sum = 0.f;
        for (int kk = lane; kk < 65; kk += 32) sum += __expf(S[rr * 65 + kk] - mx);
#pragma unroll
        for (int off = 16; off; off >>= 1) sum += __shfl_xor_sync(0xffffffffu, sum, off);
        float inv = 1.0f / sum;
        for (int kk = lane; kk < 65; kk += 32)
            S[rr * 65 + kk] = __expf(S[rr * 65 + kk] - mx) * inv;
    }
    __syncthreads();

    for (int idx = tid; idx < 64 * 64; idx += 256) {
        int l = idx >> 6, d = idx & 63;
        const float* sp = S + l * 65;
        const float* vp = Vs + d;
        float s = 0.f;
#pragma unroll
        for (int kk = 0; kk < 65; kk++) s = fmaf(sp[kk], vp[kk * 65], s);
        size_t oi = (bn * 64 + l) * 512 + h * 64 + d;
        __half hh = __float2half(s);
        Oh[oi] = hh;
        Ol[oi] = __float2half(s - __half2float(hh));
    }
}

// ================= launch =================
extern "C" void kernel_launch(void* const* d_in, const int* in_sizes, int n_in,
                              void* d_out, int out_size) {
    // Bind inputs by element count (all distinct)
    const float *x = 0, *edge = 0, *qkv_w = 0, *qkv_b = 0, *proj_w = 0, *proj_b = 0;
    const void  *mask = 0;
    for (int i = 0; i < n_in; i++) {
        switch (in_sizes[i]) {
            case 33554432: x      = (const float*)d_in[i]; break;
            case 1064960:  mask   = d_in[i];               break;
            case 4259840:  edge   = (const float*)d_in[i]; break;
            case 786432:   qkv_w  = (const float*)d_in[i]; break;
            case 1536:     qkv_b  = (const float*)d_in[i]; break;
            case 262144:   proj_w = (const float*)d_in[i]; break;
            case 512:      proj_b = (const float*)d_in[i]; break;
            default: break;
        }
    }
    float* out = (float*)d_out;

    __half *xh, *xl, *bmh, *bml, *wqh, *wph, *Oh, *Ol;
    float *Q, *KV;
    cudaGetSymbolAddress((void**)&xh, g_xh);
    cudaGetSymbolAddress((void**)&xl, g_xl);
    cudaGetSymbolAddress((void**)&bmh, g_bmh);
    cudaGetSymbolAddress((void**)&bml, g_bml);
    cudaGetSymbolAddress((void**)&wqh, g_wqh);
    cudaGetSymbolAddress((void**)&wph, g_wph);
    cudaGetSymbolAddress((void**)&Q,  g_Q);
    cudaGetSymbolAddress((void**)&KV, g_KV);
    cudaGetSymbolAddress((void**)&Oh, g_Oh);
    cudaGetSymbolAddress((void**)&Ol, g_Ol);

    cudaFuncSetAttribute(gemm_mma, cudaFuncAttributeMaxDynamicSharedMemorySize, GEMM_SMEM);
    cudaFuncSetAttribute(attn_kernel, cudaFuncAttributeMaxDynamicSharedMemorySize,
                         ATTN_SMEM_FLOATS * (int)sizeof(float));

    // Launch order arranged so the profiler's captured launch (#4) is the merged
    // QKV GEMM (the hot kernel).
    // 1. x -> fp16 hi/lo
    {
        size_t n = (size_t)BB * NBL * LQ * CC;
        split_kernel<<<(unsigned)((n + 255) / 256), 256>>>(x, xh, xl, n);
    }
    // 2. block means -> fp16 hi/lo
    block_mean_kernel<<<BB * NBL, CC>>>(x, bmh, bml);
    // 3. both weights -> fp16 (single launch)
    cvt_weights_kernel<<<(786432 + 262144 + 255) / 256, 256>>>(qkv_w, proj_w, wqh, wph);

    // 4. merged QKV GEMM: gather(kv) rows @ Wq[512,1536] -> Q (cols<512, kk<64) + KV
    gemm_mma<<<dim3(THREE_C / 128, 66560 / 128), 256, GEMM_SMEM>>>(
        xh, xl, bmh, bml, 1, wqh, THREE_C, qkv_b, 1, nullptr, 0, Q, KV);

    // 5. mask dtype detection (needed before attention only)
    detect_mask_kernel<<<1, 256>>>((const unsigned char*)mask);

    // 6. attention -> Oh/Ol (fp16 hi/lo)
    attn_kernel<<<dim3(HH, NBL, BB), 256, ATTN_SMEM_FLOATS * sizeof(float)>>>(
        Q, KV, edge, mask, Oh, Ol);

    // 7. out = O @ Wp + bp        (M=65536, N=512)
    gemm_mma<<<dim3(CC / 128, 65536 / 128), 256, GEMM_SMEM>>>(
        Oh, Ol, bmh, bml, 0, wph, CC, proj_b, 0, out, CC, nullptr, nullptr);
}

// round 12
// speedup vs baseline: 1.7138x; 1.7138x over previous
#include <cuda_runtime.h>
#include <cuda_bf16.h>
#include <cuda_fp16.h>
#include <cstdint>
#include <cstddef>

// Problem constants
#define BB   4
#define NBL  256
#define LQ   64
#define KK_  65
#define CC   512
#define HH   8
#define SCALE 0.125f
#define THREE_C 1536

// ---------------- scratch (static device globals: allocation-free) ----------------
__device__ __align__(128) __half g_xh[(size_t)BB * NBL * LQ * CC];     // 67MB
__device__ __align__(128) __half g_xl[(size_t)BB * NBL * LQ * CC];     // 67MB
__device__ __align__(128) __half g_bmh[(size_t)BB * NBL * CC];
__device__ __align__(128) __half g_bml[(size_t)BB * NBL * CC];
__device__ __align__(128) __half g_wqh[(size_t)CC * THREE_C];          // [K=512][1536] hi only
__device__ __align__(128) __half g_wph[(size_t)CC * CC];               // [512][512] hi only
__device__ __align__(128) float  g_Q [(size_t)BB * NBL * LQ * CC];     // 134MB
__device__ __align__(128) float  g_KV[(size_t)BB * NBL * KK_ * 2 * CC];// 272MB
__device__ __align__(128) __half g_Oh[(size_t)BB * NBL * LQ * CC];     // 67MB
__device__ __align__(128) __half g_Ol[(size_t)BB * NBL * LQ * CC];     // 67MB
__device__ int g_mask_mode;

// ================= PTX helpers (all baseline compute_80-era, no 'a' features) ===
__device__ __forceinline__ uint32_t smem_u32(const void* p) {
    uint32_t a;
    asm("{ .reg .u64 t; cvta.to.shared.u64 t, %1; cvt.u32.u64 %0, t; }" : "=r"(a) : "l"(p));
    return a;
}
#define CP16(d, s)   asm volatile("cp.async.cg.shared.global [%0], [%1], 16;" :: "r"(d), "l"(s))
#define CP_COMMIT()  asm volatile("cp.async.commit_group;" ::: "memory")
#define CP_WAIT2()   asm volatile("cp.async.wait_group 2;" ::: "memory")

#define LDSM4(d, addr)                                                           \
    asm volatile("ldmatrix.sync.aligned.m8n8.x4.shared.b16 {%0,%1,%2,%3}, [%4];" \
        : "=r"((d)[0]), "=r"((d)[1]), "=r"((d)[2]), "=r"((d)[3]) : "r"(addr))
#define LDSM4T(d, addr)                                                          \
    asm volatile("ldmatrix.sync.aligned.m8n8.x4.trans.shared.b16 {%0,%1,%2,%3}, [%4];" \
        : "=r"((d)[0]), "=r"((d)[1]), "=r"((d)[2]), "=r"((d)[3]) : "r"(addr))

#define MMA16816F16(acc, a, b)                                                   \
    asm volatile("mma.sync.aligned.m16n8k16.row.col.f32.f16.f16.f32 "            \
        "{%0,%1,%2,%3}, {%4,%5,%6,%7}, {%8,%9}, {%0,%1,%2,%3};"                  \
        : "+f"((acc)[0]), "+f"((acc)[1]), "+f"((acc)[2]), "+f"((acc)[3])         \
        : "r"((a)[0]), "r"((a)[1]), "r"((a)[2]), "r"((a)[3]),                    \
          "r"((b)[0]), "r"((b)[1]))

// ================= small kernels =================
__global__ void detect_mask_kernel(const unsigned char* __restrict__ m) {
    __shared__ int sA, s0;
    if (threadIdx.x == 0) { sA = 0; s0 = 0; }
    __syncthreads();
    int a = 0, z = 0;
    for (int i = threadIdx.x; i < 4096; i += blockDim.x) {
        int v = m[i];
        if ((i & 3) == 1) a |= v;
        if ((i & 3) == 0) z |= v;
    }
    if (a) atomicOr(&sA, 1);
    if (z) atomicOr(&s0, 1);
    __syncthreads();
    if (threadIdx.x == 0) g_mask_mode = sA ? 0 : (s0 ? 1 : 2);
}

// block mean -> fp16 hi/lo directly
__global__ void block_mean_kernel(const float* __restrict__ x,
                                  __half* __restrict__ bmh, __half* __restrict__ bml) {
    int blk = blockIdx.x, c = threadIdx.x;
    const float* base = x + (size_t)blk * LQ * CC + c;
    float s = 0.f;
#pragma unroll
    for (int l = 0; l < LQ; l++) s += base[(size_t)l * CC];
    float m = s * (1.0f / 64.0f);
    __half h = __float2half(m);
    bmh[(size_t)blk * CC + c] = h;
    bml[(size_t)blk * CC + c] = __float2half(m - __half2float(h));
}

// fp32 -> fp16 hi + fp16 lo
__global__ void split_kernel(const float* __restrict__ src,
                             __half* __restrict__ dh,
                             __half* __restrict__ dl, size_t n) {
    size_t i = (size_t)blockIdx.x * blockDim.x + threadIdx.x;
    if (i >= n) return;
    float v = src[i];
    __half h = __float2half(v);
    dh[i] = h;
    dl[i] = __float2half(v - __half2float(h));
}

// both weight matrices -> fp16 hi, one launch
__global__ void cvt_weights_kernel(const float* __restrict__ wq,
                                   const float* __restrict__ wp,
                                   __half* __restrict__ wqh, __half* __restrict__ wph) {
    size_t i = (size_t)blockIdx.x * blockDim.x + threadIdx.x;
    const size_t n1 = (size_t)CC * THREE_C;           // 786432
    const size_t n2 = (size_t)CC * CC;                // 262144
    if (i < n1) wqh[i] = __float2half(wq[i]);
    else if (i < n1 + n2) wph[i - n1] = __float2half(wp[i - n1]);
}

// ================= mma.sync fp16 GEMM (2-product compensation) =================
// epi_mode 0: C[M,N] + bias -> C (ldc)
// epi_mode 1: merged QKV: col<512 -> Q (skip kk==64 rows), col>=512 -> KV
// CTA 128x128, 8 warps (2m x 4n). K=512 in 16 chunks of 32; 3-stage cp.async.
// Mainloop = R10's proven structure: wait_group 2, compute, sync, load c+3.
#define KCHUNK     32
#define NCHUNK     16
#define A_STRIDE_B 80
#define B_STRIDE_B 272
#define A_HALF     10240                  // 128 * 80
#define B_OFF      20480                  // 2 * A_HALF
#define STAGE_BYTES 29184                 // 2*A_HALF + 32*272
#define GEMM_SMEM  (3 * STAGE_BYTES)      // 87552 -> 2 CTAs/SM

__device__ __forceinline__ void a_ptrs(
    const __half* __restrict__ Ah, const __half* __restrict__ Al,
    const __half* __restrict__ bmh, const __half* __restrict__ bml,
    int gmode, int gr,
    const __half*& ph, const __half*& pl)
{
    if (gmode == 0) { size_t o = (size_t)gr * CC; ph = Ah + o; pl = Al + o; return; }
    int b  = gr / (NBL * KK_);
    int t  = gr - b * (NBL * KK_);
    int nb = t / KK_;
    int kk = t - nb * KK_;
    if (kk < LQ) { size_t o = ((size_t)(b * NBL + nb) * LQ + kk) * CC; ph = Ah + o; pl = Al + o; }
    else         { size_t o = (size_t)(b * NBL + nb) * CC;             ph = bmh + o; pl = bml + o; }
}

__global__ __launch_bounds__(256) void gemm_mma(
    const __half* __restrict__ Ah, const __half* __restrict__ Al,
    const __half* __restrict__ bmh, const __half* __restrict__ bml,
    int gmode,
    const __half* __restrict__ Bh, int ldB,
    const float* __restrict__ bias,
    int epi_mode,
    float* __restrict__ C, int ldc,
    float* __restrict__ Qp, float* __restrict__ KVp)
{
    extern __shared__ __align__(128) char smem[];
    const uint32_t sb = smem_u32(smem);
    const int tid = threadIdx.x, wid = tid >> 5, lane = tid & 31;
    const int warp_m = wid >> 2, warp_n = wid & 3;
    const int rowBase = blockIdx.y * 128;
    const int colBase = blockIdx.x * 128;
    const int g = lane >> 3, r = lane & 7;

    float acc[4][4][4];
#pragma unroll
    for (int ma = 0; ma < 4; ma++)
#pragma unroll
        for (int na = 0; na < 4; na++)
#pragma unroll
            for (int q = 0; q < 4; q++) acc[ma][na][q] = 0.f;

    const uint32_t aOff = (uint32_t)((warp_m * 64 + (g & 1) * 8 + r) * A_STRIDE_B + (g >> 1) * 16);
    const uint32_t bOff = (uint32_t)(B_OFF + ((g & 1) * 8 + r) * B_STRIDE_B
                                     + (warp_n * 32 + (g >> 1) * 8) * 2);

    auto load_chunk = [&](int k0, uint32_t stBase) {
        // A: 128 rows x 32 fp16 (64B) = 4 x 16B per row, hi & lo
#pragma unroll
        for (int i = tid; i < 512; i += 256) {
            int row = i >> 2, seg = i & 3;
            const __half *ph, *pl;
            a_ptrs(Ah, Al, bmh, bml, gmode, rowBase + row, ph, pl);
            uint32_t da = stBase + row * A_STRIDE_B + seg * 16;
            CP16(da,          ph + k0 + seg * 8);
            CP16(da + A_HALF, pl + k0 + seg * 8);
        }
        // B: 32 rows x 128 fp16 (256B) = 16 x 16B per row, hi only
#pragma unroll
        for (int i = tid; i < 512; i += 256) {
            int row = i >> 4, seg = i & 15;
            size_t off = (size_t)(k0 + row) * ldB + colBase + seg * 8;
            CP16(stBase + B_OFF + row * B_STRIDE_B + seg * 16, Bh + off);
        }
    };

    // prologue: stages 0..2 (load-ahead 3, as in the proven R10 loop)
#pragma unroll
    for (int s = 0; s < 3; s++) {
        load_chunk(s * KCHUNK, sb + s * STAGE_BYTES);
        CP_COMMIT();
    }

    for (int c = 0; c < NCHUNK; c++) {
        CP_WAIT2();
        __syncthreads();
        const uint32_t st = sb + (c % 3) * STAGE_BYTES;

#pragma unroll
        for (int ks = 0; ks < 2; ks++) {
            uint32_t ah[4][4], al[4][4], bh[2][4];
#pragma unroll
            for (int ma = 0; ma < 4; ma++) {
                uint32_t ad = st + aOff + ma * (16 * A_STRIDE_B) + ks * 32;
                LDSM4(ah[ma], ad);
                LDSM4(al[ma], ad + A_HALF);
            }
#pragma unroll
            for (int p = 0; p < 2; p++) {
                uint32_t bd = st + bOff + ks * (16 * B_STRIDE_B) + p * 32;
                LDSM4T(bh[p], bd);
            }
#pragma unroll
            for (int ma = 0; ma < 4; ma++)
#pragma unroll
                for (int na = 0; na < 4; na++) {
                    int p = na >> 1, q = (na & 1) * 2;
                    MMA16816F16(acc[ma][na], ah[ma], bh[p] + q);
                    MMA16816F16(acc[ma][na], al[ma], bh[p] + q);
                }
        }
        __syncthreads();
        if (c + 3 < NCHUNK) load_chunk((c + 3) * KCHUNK, st);
        CP_COMMIT();   // keep group count aligned even when nothing issued
    }

    // ---- epilogue ----
    if (epi_mode == 0) {
#pragma unroll
        for (int ma = 0; ma < 4; ma++) {
            int gr = rowBase + warp_m * 64 + ma * 16 + (lane >> 2);
#pragma unroll
            for (int na = 0; na < 4; na++) {
                int gc = colBase + warp_n * 32 + na * 8 + 2 * (lane & 3);
                float b0 = bias[gc], b1 = bias[gc + 1];
                float2 v0 = make_float2(acc[ma][na][0] + b0, acc[ma][na][1] + b1);
                float2 v1 = make_float2(acc[ma][na][2] + b0, acc[ma][na][3] + b1);
                *(float2*)&C[(size_t)gr * ldc + gc]       = v0;
                *(float2*)&C[(size_t)(gr + 8) * ldc + gc] = v1;
            }
        }
    } else {
        // merged QKV routing; whole CTA column block is Q (colBase<512) or KV.
        const bool isQ = (colBase < 512);
#pragma unroll
        for (int ma = 0; ma < 4; ma++) {
            int gr0 = rowBase + warp_m * 64 + ma * 16 + (lane >> 2);
#pragma unroll
            for (int rr = 0; rr < 2; rr++) {
                int gr = gr0 + rr * 8;
                int b  = gr / (NBL * KK_);
                int t  = gr - b * (NBL * KK_);
                int nb = t / KK_;
                int kk = t - nb * KK_;
                size_t bn = (size_t)b * NBL + nb;
                float* dst;
                int cshift;
                if (isQ) {
                    if (kk >= LQ) continue;             // block-node row: no Q output
                    dst = Qp + (bn * 64 + kk) * 512;
                    cshift = 0;
                } else {
                    dst = KVp + (bn * 65 + kk) * 1024;
                    cshift = 512;
                }
#pragma unroll
                for (int na = 0; na < 4; na++) {
                    int gc = colBase + warp_n * 32 + na * 8 + 2 * (lane & 3);
                    float b0 = bias[gc], b1 = bias[gc + 1];
                    float2 v = make_float2(acc[ma][na][rr * 2] + b0,
                                           acc[ma][na][rr * 2 + 1] + b1);
                    *(float2*)&dst[gc - cshift] = v;
                }
            }
        }
    }
}

// ================= fused per-(b,nb,h) attention (fp32, outputs fp16 hi/lo) ========
#define ATTN_SMEM_FLOATS (64 * 64 + 65 * 65 + 65 * 65 + 64 * 65)

__global__ __launch_bounds__(256) void attn_kernel(
    const float* __restrict__ Qb, const float* __restrict__ KVb,
    const float* __restrict__ edge, const void* __restrict__ maskp,
    __half* __restrict__ Oh, __half* __restrict__ Ol)
{
    extern __shared__ float sm[];
    float* Qs = sm;
    float* Ks = Qs + 64 * 64;
    float* Vs = Ks + 65 * 65;
    float* S  = Vs + 65 * 65;

    const int h  = blockIdx.x;
    const int nb = blockIdx.y;
    const int b  = blockIdx.z;
    const int tid = threadIdx.x;
    const size_t bn = (size_t)b * NBL + nb;

    for (int idx = tid; idx < 64 * 64; idx += 256) {
        int l = idx >> 6, d = idx & 63;
        Qs[idx] = Qb[(bn * 64 + l) * 512 + h * 64 + d];
    }
    for (int idx = tid; idx < 65 * 64; idx += 256) {
        int kk = idx >> 6, d = idx & 63;
        size_t rb = (bn * 65 + kk) * 1024 + h * 64 + d;
        Ks[kk * 65 + d] = KVb[rb];
        Vs[kk * 65 + d] = KVb[rb + 512];
    }
    __syncthreads();

    const int mode = g_mask_mode;

    for (int idx = tid; idx < 64 * 65; idx += 256) {
        int l  = idx / 65;
        int kk = idx - l * 65;
        const float* q  = Qs + l * 64;
        const float* kp = Ks + kk * 65;
        float s = 0.f;
#pragma unroll
        for (int d = 0; d < 64; d++) s = fmaf(q[d], kp[d], s);
        s *= SCALE;

        float bias;
        if (kk == 64 || kk == l) bias = 1.0f;
        else bias = edge[((((size_t)nb * 64) + l) * 65 + kk) * 4 + 3];
        s += bias;

        size_t mi = ((size_t)nb * 64 + l) * 65 + kk;
        bool ok;
        if (mode == 0)      ok = ((const unsigned char*)maskp)[mi] != 0;
        else if (mode == 1) ok = ((const int*)maskp)[mi] != 0;
        else                ok = ((const float*)maskp)[mi] != 0.0f;

        S[l * 65 + kk] = ok ? s : -1.0e9f;
    }
    __syncthreads();

    const int w = tid >> 5, lane = tid & 31;
    for (int rr = w; rr < 64; rr += 8) {
        float mx = -1.0e30f;
        for (int kk = lane; kk < 65; kk += 32) mx = fmaxf(mx, S[rr * 65 + kk]);
#pragma unroll
        for (int off = 16; off; off >>= 1) mx = fmaxf(mx, __shfl_xor_sync(0xffffffffu, mx, off));
        float sum = 0.f;
        for (int kk = lane; kk < 65; kk += 32) sum += __expf(S[rr * 65 + kk] - mx);
#pragma unroll
        for (int off = 16; off; off >>= 1) sum += __shfl_xor_sync(0xffffffffu, sum, off);
        float inv = 1.0f / sum;
        for (int kk = lane; kk < 65; kk += 32)
            S[rr * 65 + kk] = __expf(S[rr * 65 + kk] - mx) * inv;
    }
    __syncthreads();

    for (int idx = tid; idx < 64 * 64; idx += 256) {
        int l = idx >> 6, d = idx & 63;
        const float* sp = S + l * 65;
        const float* vp = Vs + d;
        float s = 0.f;
#pragma unroll
        for (int kk = 0; kk < 65; kk++) s = fmaf(sp[kk], vp[kk * 65], s);
        size_t oi = (bn * 64 + l) * 512 + h * 64 + d;
        __half hh = __float2half(s);
        Oh[oi] = hh;
        Ol[oi] = __float2half(s - __half2float(hh));
    }
}

// ================= launch =================
extern "C" void kernel_launch(void* const* d_in, const int* in_sizes, int n_in,
                              void* d_out, int out_size) {
    // Bind inputs by element count (all distinct)
    const float *x = 0, *edge = 0, *qkv_w = 0, *qkv_b = 0, *proj_w = 0, *proj_b = 0;
    const void  *mask = 0;
    for (int i = 0; i < n_in; i++) {
        switch (in_sizes[i]) {
            case 33554432: x      = (const float*)d_in[i]; break;
            case 1064960:  mask   = d_in[i];               break;
            case 4259840:  edge   = (const float*)d_in[i]; break;
            case 786432:   qkv_w  = (const float*)d_in[i]; break;
            case 1536:     qkv_b  = (const float*)d_in[i]; break;
            case 262144:   proj_w = (const float*)d_in[i]; break;
            case 512:      proj_b = (const float*)d_in[i]; break;
            default: break;
        }
    }
    float* out = (float*)d_out;

    __half *xh, *xl, *bmh, *bml, *wqh, *wph, *Oh, *Ol;
    float *Q, *KV;
    cudaGetSymbolAddress((void**)&xh, g_xh);
    cudaGetSymbolAddress((void**)&xl, g_xl);
    cudaGetSymbolAddress((void**)&bmh, g_bmh);
    cudaGetSymbolAddress((void**)&bml, g_bml);
    cudaGetSymbolAddress((void**)&wqh, g_wqh);
    cudaGetSymbolAddress((void**)&wph, g_wph);
    cudaGetSymbolAddress((void**)&Q,  g_Q);
    cudaGetSymbolAddress((void**)&KV, g_KV);
    cudaGetSymbolAddress((void**)&Oh, g_Oh);
    cudaGetSymbolAddress((void**)&Ol, g_Ol);

    cudaFuncSetAttribute(gemm_mma, cudaFuncAttributeMaxDynamicSharedMemorySize, GEMM_SMEM);
    cudaFuncSetAttribute(attn_kernel, cudaFuncAttributeMaxDynamicSharedMemorySize,
                         ATTN_SMEM_FLOATS * (int)sizeof(float));

    // Launch order: profiler's captured launch (#4) = merged QKV GEMM (hot kernel).
    // 1. x -> fp16 hi/lo
    {
        size_t n = (size_t)BB * NBL * LQ * CC;
        split_kernel<<<(unsigned)((n + 255) / 256), 256>>>(x, xh, xl, n);
    }
    // 2. block means -> fp16 hi/lo
    block_mean_kernel<<<BB * NBL, CC>>>(x, bmh, bml);
    // 3. both weights -> fp16 (single launch)
    cvt_weights_kernel<<<(786432 + 262144 + 255) / 256, 256>>>(qkv_w, proj_w, wqh, wph);

    // 4. merged QKV GEMM: gather(kv) rows @ Wq[512,1536] -> Q (cols<512, kk<64) + KV
    gemm_mma<<<dim3(THREE_C / 128, 66560 / 128), 256, GEMM_SMEM>>>(
        xh, xl, bmh, bml, 1, wqh, THREE_C, qkv_b, 1, nullptr, 0, Q, KV);

    // 5. mask dtype detection (needed before attention only)
    detect_mask_kernel<<<1, 256>>>((const unsigned char*)mask);

    // 6. attention -> Oh/Ol (fp16 hi/lo)
    attn_kernel<<<dim3(HH, NBL, BB), 256, ATTN_SMEM_FLOATS * sizeof(float)>>>(
        Q, KV, edge, mask, Oh, Ol);

    // 7. out = O @ Wp + bp        (M=65536, N=512)
    gemm_mma<<<dim3(CC / 128, 65536 / 128), 256, GEMM_SMEM>>>(
        Oh, Ol, bmh, bml, 0, wph, CC, proj_b, 0, out, CC, nullptr, nullptr);
}

// round 13
// speedup vs baseline: 2.0118x; 1.1739x over previous
#include <cuda_runtime.h>
#include <cuda_bf16.h>
#include <cuda_fp16.h>
#include <cstdint>
#include <cstddef>

// Problem constants
#define BB   4
#define NBL  256
#define LQ   64
#define KK_  65
#define CC   512
#define HH   8
#define SCALE 0.125f
#define THREE_C 1536

// ---------------- scratch (static device globals: allocation-free) ----------------
__device__ __align__(128) __half g_xh[(size_t)BB * NBL * LQ * CC];     // 67MB
__device__ __align__(128) __half g_xl[(size_t)BB * NBL * LQ * CC];     // 67MB
__device__ __align__(128) __half g_bmh[(size_t)BB * NBL * CC];
__device__ __align__(128) __half g_bml[(size_t)BB * NBL * CC];
__device__ __align__(128) __half g_wqh[(size_t)CC * THREE_C];          // [K=512][1536] hi only
__device__ __align__(128) __half g_wph[(size_t)CC * CC];               // [512][512] hi only
__device__ __align__(128) __half g_Qh[(size_t)BB * NBL * LQ * CC];     // 67MB
__device__ __align__(128) __half g_Ql[(size_t)BB * NBL * LQ * CC];     // 67MB
__device__ __align__(128) __half g_KVh[(size_t)BB * NBL * KK_ * 2 * CC]; // 136MB
__device__ __align__(128) __half g_KVl[(size_t)BB * NBL * KK_ * 2 * CC]; // 136MB
__device__ __align__(128) __half g_Oh[(size_t)BB * NBL * LQ * CC];     // 67MB
__device__ __align__(128) __half g_Ol[(size_t)BB * NBL * LQ * CC];     // 67MB
__device__ int g_mask_mode;

// ================= PTX helpers (all baseline compute_80-era, no 'a' features) ===
__device__ __forceinline__ uint32_t smem_u32(const void* p) {
    uint32_t a;
    asm("{ .reg .u64 t; cvta.to.shared.u64 t, %1; cvt.u32.u64 %0, t; }" : "=r"(a) : "l"(p));
    return a;
}
#define CP16(d, s)   asm volatile("cp.async.cg.shared.global [%0], [%1], 16;" :: "r"(d), "l"(s))
#define CP_COMMIT()  asm volatile("cp.async.commit_group;" ::: "memory")
#define CP_WAIT2()   asm volatile("cp.async.wait_group 2;" ::: "memory")

#define LDSM4(d, addr)                                                           \
    asm volatile("ldmatrix.sync.aligned.m8n8.x4.shared.b16 {%0,%1,%2,%3}, [%4];" \
        : "=r"((d)[0]), "=r"((d)[1]), "=r"((d)[2]), "=r"((d)[3]) : "r"(addr))
#define LDSM4T(d, addr)                                                          \
    asm volatile("ldmatrix.sync.aligned.m8n8.x4.trans.shared.b16 {%0,%1,%2,%3}, [%4];" \
        : "=r"((d)[0]), "=r"((d)[1]), "=r"((d)[2]), "=r"((d)[3]) : "r"(addr))

#define MMA16816F16(acc, a, b)                                                   \
    asm volatile("mma.sync.aligned.m16n8k16.row.col.f32.f16.f16.f32 "            \
        "{%0,%1,%2,%3}, {%4,%5,%6,%7}, {%8,%9}, {%0,%1,%2,%3};"                  \
        : "+f"((acc)[0]), "+f"((acc)[1]), "+f"((acc)[2]), "+f"((acc)[3])         \
        : "r"((a)[0]), "r"((a)[1]), "r"((a)[2]), "r"((a)[3]),                    \
          "r"((b)[0]), "r"((b)[1]))

// ================= small kernels =================
__global__ void detect_mask_kernel(const unsigned char* __restrict__ m) {
    __shared__ int sA, s0;
    if (threadIdx.x == 0) { sA = 0; s0 = 0; }
    __syncthreads();
    int a = 0, z = 0;
    for (int i = threadIdx.x; i < 4096; i += blockDim.x) {
        int v = m[i];
        if ((i & 3) == 1) a |= v;
        if ((i & 3) == 0) z |= v;
    }
    if (a) atomicOr(&sA, 1);
    if (z) atomicOr(&s0, 1);
    __syncthreads();
    if (threadIdx.x == 0) g_mask_mode = sA ? 0 : (s0 ? 1 : 2);
}

// block mean -> fp16 hi/lo directly
__global__ void block_mean_kernel(const float* __restrict__ x,
                                  __half* __restrict__ bmh, __half* __restrict__ bml) {
    int blk = blockIdx.x, c = threadIdx.x;
    const float* base = x + (size_t)blk * LQ * CC + c;
    float s = 0.f;
#pragma unroll
    for (int l = 0; l < LQ; l++) s += base[(size_t)l * CC];
    float m = s * (1.0f / 64.0f);
    __half h = __float2half(m);
    bmh[(size_t)blk * CC + c] = h;
    bml[(size_t)blk * CC + c] = __float2half(m - __half2float(h));
}

// fp32 -> fp16 hi + fp16 lo
__global__ void split_kernel(const float* __restrict__ src,
                             __half* __restrict__ dh,
                             __half* __restrict__ dl, size_t n) {
    size_t i = (size_t)blockIdx.x * blockDim.x + threadIdx.x;
    if (i >= n) return;
    float v = src[i];
    __half h = __float2half(v);
    dh[i] = h;
    dl[i] = __float2half(v - __half2float(h));
}

// both weight matrices -> fp16 hi, one launch
__global__ void cvt_weights_kernel(const float* __restrict__ wq,
                                   const float* __restrict__ wp,
                                   __half* __restrict__ wqh, __half* __restrict__ wph) {
    size_t i = (size_t)blockIdx.x * blockDim.x + threadIdx.x;
    const size_t n1 = (size_t)CC * THREE_C;
    const size_t n2 = (size_t)CC * CC;
    if (i < n1) wqh[i] = __float2half(wq[i]);
    else if (i < n1 + n2) wph[i - n1] = __float2half(wp[i - n1]);
}

// ================= mma.sync fp16 GEMM (2-product compensation) =================
// epi_mode 0: fp32 C[M,N] + bias -> C (ldc)
// epi_mode 1: merged QKV -> fp16 hi/lo: col<512 -> Qh/Ql (skip kk==64), col>=512 -> KVh/KVl
#define KCHUNK     32
#define NCHUNK     16
#define A_STRIDE_B 80
#define B_STRIDE_B 272
#define A_HALF     10240
#define B_OFF      20480
#define STAGE_BYTES 29184
#define GEMM_SMEM  (3 * STAGE_BYTES)      // 87552 -> 2 CTAs/SM

__device__ __forceinline__ void a_ptrs(
    const __half* __restrict__ Ah, const __half* __restrict__ Al,
    const __half* __restrict__ bmh, const __half* __restrict__ bml,
    int gmode, int gr,
    const __half*& ph, const __half*& pl)
{
    if (gmode == 0) { size_t o = (size_t)gr * CC; ph = Ah + o; pl = Al + o; return; }
    int b  = gr / (NBL * KK_);
    int t  = gr - b * (NBL * KK_);
    int nb = t / KK_;
    int kk = t - nb * KK_;
    if (kk < LQ) { size_t o = ((size_t)(b * NBL + nb) * LQ + kk) * CC; ph = Ah + o; pl = Al + o; }
    else         { size_t o = (size_t)(b * NBL + nb) * CC;             ph = bmh + o; pl = bml + o; }
}

__global__ __launch_bounds__(256) void gemm_mma(
    const __half* __restrict__ Ah, const __half* __restrict__ Al,
    const __half* __restrict__ bmh, const __half* __restrict__ bml,
    int gmode,
    const __half* __restrict__ Bh, int ldB,
    const float* __restrict__ bias,
    int epi_mode,
    float* __restrict__ C, int ldc,
    __half* __restrict__ QhP, __half* __restrict__ QlP,
    __half* __restrict__ KVhP, __half* __restrict__ KVlP)
{
    extern __shared__ __align__(128) char smem[];
    const uint32_t sb = smem_u32(smem);
    const int tid = threadIdx.x, wid = tid >> 5, lane = tid & 31;
    const int warp_m = wid >> 2, warp_n = wid & 3;
    const int rowBase = blockIdx.y * 128;
    const int colBase = blockIdx.x * 128;
    const int g = lane >> 3, r = lane & 7;

    float acc[4][4][4];
#pragma unroll
    for (int ma = 0; ma < 4; ma++)
#pragma unroll
        for (int na = 0; na < 4; na++)
#pragma unroll
            for (int q = 0; q < 4; q++) acc[ma][na][q] = 0.f;

    const uint32_t aOff = (uint32_t)((warp_m * 64 + (g & 1) * 8 + r) * A_STRIDE_B + (g >> 1) * 16);
    const uint32_t bOff = (uint32_t)(B_OFF + ((g & 1) * 8 + r) * B_STRIDE_B
                                     + (warp_n * 32 + (g >> 1) * 8) * 2);

    auto load_chunk = [&](int k0, uint32_t stBase) {
#pragma unroll
        for (int i = tid; i < 512; i += 256) {
            int row = i >> 2, seg = i & 3;
            const __half *ph, *pl;
            a_ptrs(Ah, Al, bmh, bml, gmode, rowBase + row, ph, pl);
            uint32_t da = stBase + row * A_STRIDE_B + seg * 16;
            CP16(da,          ph + k0 + seg * 8);
            CP16(da + A_HALF, pl + k0 + seg * 8);
        }
#pragma unroll
        for (int i = tid; i < 512; i += 256) {
            int row = i >> 4, seg = i & 15;
            size_t off = (size_t)(k0 + row) * ldB + colBase + seg * 8;
            CP16(stBase + B_OFF + row * B_STRIDE_B + seg * 16, Bh + off);
        }
    };

#pragma unroll
    for (int s = 0; s < 3; s++) {
        load_chunk(s * KCHUNK, sb + s * STAGE_BYTES);
        CP_COMMIT();
    }

    for (int c = 0; c < NCHUNK; c++) {
        CP_WAIT2();
        __syncthreads();
        const uint32_t st = sb + (c % 3) * STAGE_BYTES;

#pragma unroll
        for (int ks = 0; ks < 2; ks++) {
            uint32_t ah[4][4], al[4][4], bh[2][4];
#pragma unroll
            for (int ma = 0; ma < 4; ma++) {
                uint32_t ad = st + aOff + ma * (16 * A_STRIDE_B) + ks * 32;
                LDSM4(ah[ma], ad);
                LDSM4(al[ma], ad + A_HALF);
            }
#pragma unroll
            for (int p = 0; p < 2; p++) {
                uint32_t bd = st + bOff + ks * (16 * B_STRIDE_B) + p * 32;
                LDSM4T(bh[p], bd);
            }
#pragma unroll
            for (int ma = 0; ma < 4; ma++)
#pragma unroll
                for (int na = 0; na < 4; na++) {
                    int p = na >> 1, q = (na & 1) * 2;
                    MMA16816F16(acc[ma][na], ah[ma], bh[p] + q);
                    MMA16816F16(acc[ma][na], al[ma], bh[p] + q);
                }
        }
        __syncthreads();
        if (c + 3 < NCHUNK) load_chunk((c + 3) * KCHUNK, st);
        CP_COMMIT();
    }

    // ---- epilogue ----
    if (epi_mode == 0) {
#pragma unroll
        for (int ma = 0; ma < 4; ma++) {
            int gr = rowBase + warp_m * 64 + ma * 16 + (lane >> 2);
#pragma unroll
            for (int na = 0; na < 4; na++) {
                int gc = colBase + warp_n * 32 + na * 8 + 2 * (lane & 3);
                float b0 = bias[gc], b1 = bias[gc + 1];
                float2 v0 = make_float2(acc[ma][na][0] + b0, acc[ma][na][1] + b1);
                float2 v1 = make_float2(acc[ma][na][2] + b0, acc[ma][na][3] + b1);
                *(float2*)&C[(size_t)gr * ldc + gc]       = v0;
                *(float2*)&C[(size_t)(gr + 8) * ldc + gc] = v1;
            }
        }
    } else {
        const bool isQ = (colBase < 512);
#pragma unroll
        for (int ma = 0; ma < 4; ma++) {
            int gr0 = rowBase + warp_m * 64 + ma * 16 + (lane >> 2);
#pragma unroll
            for (int rr = 0; rr < 2; rr++) {
                int gr = gr0 + rr * 8;
                int b  = gr / (NBL * KK_);
                int t  = gr - b * (NBL * KK_);
                int nb = t / KK_;
                int kk = t - nb * KK_;
                size_t bn = (size_t)b * NBL + nb;
                __half *dh, *dl;
                int cshift;
                if (isQ) {
                    if (kk >= LQ) continue;
                    size_t o = (bn * 64 + kk) * 512;
                    dh = QhP + o; dl = QlP + o; cshift = 0;
                } else {
                    size_t o = (bn * 65 + kk) * 1024;
                    dh = KVhP + o; dl = KVlP + o; cshift = 512;
                }
#pragma unroll
                for (int na = 0; na < 4; na++) {
                    int gc = colBase + warp_n * 32 + na * 8 + 2 * (lane & 3);
                    float v0 = acc[ma][na][rr * 2]     + bias[gc];
                    float v1 = acc[ma][na][rr * 2 + 1] + bias[gc + 1];
                    __half h0 = __float2half(v0), h1 = __float2half(v1);
                    __half l0 = __float2half(v0 - __half2float(h0));
                    __half l1 = __float2half(v1 - __half2float(h1));
                    int cc = gc - cshift;
                    *(__half2*)&dh[cc] = __halves2half2(h0, h1);
                    *(__half2*)&dl[cc] = __halves2half2(l0, l1);
                }
            }
        }
    }
}

// ================= mma.sync attention per (b,nb,h) ==========================
// K padded to 96 rows (zeros). Scores: (Qh,Ql)x(Kh,Kl) 3-product. AV: (Ah,Al)xVh.
// smem byte offsets (fp16 strides: Q/K/V 72, A 104; S fp32 stride 100)
#define AT_QH 0
#define AT_QL 9216
#define AT_KH 18432
#define AT_KL 32256
#define AT_VH 46080
#define AT_SS 59904
#define AT_AH 85504
#define AT_AL 98816
#define AT_SMEM 112128

__global__ __launch_bounds__(256) void attn_mma(
    const __half* __restrict__ Qhg, const __half* __restrict__ Qlg,
    const __half* __restrict__ KVhg, const __half* __restrict__ KVlg,
    const float* __restrict__ edge, const void* __restrict__ maskp,
    __half* __restrict__ Ohg, __half* __restrict__ Olg)
{
    extern __shared__ __align__(128) char sm[];
    const uint32_t sb = smem_u32(sm);
    float* S = (float*)(sm + AT_SS);

    const int h  = blockIdx.x;
    const int nb = blockIdx.y;
    const int b  = blockIdx.z;
    const int tid = threadIdx.x, wid = tid >> 5, lane = tid & 31;
    const int g = lane >> 3, r = lane & 7;
    const size_t bn = (size_t)b * NBL + nb;

    // ---- load Q (64x64) and K/V (65x64 + zero pad to 96) ----
    for (int i = tid; i < 512; i += 256) {
        int row = i >> 3, ch = i & 7;
        size_t go = (bn * 64 + row) * 512 + h * 64 + ch * 8;
        *(uint4*)(sm + AT_QH + row * 144 + ch * 16) = *(const uint4*)&Qhg[go];
        *(uint4*)(sm + AT_QL + row * 144 + ch * 16) = *(const uint4*)&Qlg[go];
    }
    for (int i = tid; i < 768; i += 256) {
        int row = i >> 3, ch = i & 7;
        uint4 kh = {0,0,0,0}, kl = {0,0,0,0}, vh = {0,0,0,0};
        if (row < 65) {
            size_t go = (bn * 65 + row) * 1024 + h * 64 + ch * 8;
            kh = *(const uint4*)&KVhg[go];
            kl = *(const uint4*)&KVlg[go];
            vh = *(const uint4*)&KVhg[go + 512];
        }
        *(uint4*)(sm + AT_KH + row * 144 + ch * 16) = kh;
        *(uint4*)(sm + AT_KL + row * 144 + ch * 16) = kl;
        *(uint4*)(sm + AT_VH + row * 144 + ch * 16) = vh;
    }
    __syncthreads();

    // ---- scores: S[64][96] = Q @ K^T (3-product) ----
    const int warp_m = wid & 3, warp_n = wid >> 2;
    const int m0 = warp_m * 16, n0 = warp_n * 48;
    {
        float sacc[6][4];
#pragma unroll
        for (int nt = 0; nt < 6; nt++)
#pragma unroll
            for (int q = 0; q < 4; q++) sacc[nt][q] = 0.f;

#pragma unroll
        for (int ks = 0; ks < 4; ks++) {
            uint32_t qh4[4], ql4[4], kh4[3][4], kl4[3][4];
            uint32_t qa = sb + AT_QH + (m0 + (g & 1) * 8 + r) * 144 + (g >> 1) * 16 + ks * 32;
            LDSM4(qh4, qa);
            LDSM4(ql4, qa + (AT_QL - AT_QH));
#pragma unroll
            for (int t = 0; t < 3; t++) {
                uint32_t ka = sb + AT_KH + (n0 + t * 16 + (g & 1) * 8 + r) * 144
                              + (g >> 1) * 16 + ks * 32;
                LDSM4(kh4[t], ka);
                LDSM4(kl4[t], ka + (AT_KL - AT_KH));
            }
#pragma unroll
            for (int nt = 0; nt < 6; nt++) {
                int t = nt >> 1, o = nt & 1;
                uint32_t bfh[2] = { kh4[t][o], kh4[t][o + 2] };
                uint32_t bfl[2] = { kl4[t][o], kl4[t][o + 2] };
                MMA16816F16(sacc[nt], qh4, bfh);
                MMA16816F16(sacc[nt], ql4, bfh);
                MMA16816F16(sacc[nt], qh4, bfl);
            }
        }
        // store S (stride 100 fp32)
#pragma unroll
        for (int nt = 0; nt < 6; nt++) {
            int col = n0 + nt * 8 + (lane & 3) * 2;
            int row = m0 + (lane >> 2);
            *(float2*)&S[row * 100 + col]       = make_float2(sacc[nt][0], sacc[nt][1]);
            *(float2*)&S[(row + 8) * 100 + col] = make_float2(sacc[nt][2], sacc[nt][3]);
        }
    }
    __syncthreads();

    // ---- scale + bias + mask (cols < 65) ----
    const int mode = g_mask_mode;
    for (int idx = tid; idx < 64 * 65; idx += 256) {
        int l  = idx / 65;
        int kk = idx - l * 65;
        float s = S[l * 100 + kk] * SCALE;
        float bias;
        if (kk == 64 || kk == l) bias = 1.0f;
        else bias = edge[((((size_t)nb * 64) + l) * 65 + kk) * 4 + 3];
        s += bias;
        size_t mi = ((size_t)nb * 64 + l) * 65 + kk;
        bool ok;
        if (mode == 0)      ok = ((const unsigned char*)maskp)[mi] != 0;
        else if (mode == 1) ok = ((const int*)maskp)[mi] != 0;
        else                ok = ((const float*)maskp)[mi] != 0.0f;
        S[l * 100 + kk] = ok ? s : -1.0e9f;
    }
    __syncthreads();

    // ---- softmax rows (cols < 65) ----
    for (int rr = wid; rr < 64; rr += 8) {
        float mx = -1.0e30f;
        for (int kk = lane; kk < 65; kk += 32) mx = fmaxf(mx, S[rr * 100 + kk]);
#pragma unroll
        for (int off = 16; off; off >>= 1) mx = fmaxf(mx, __shfl_xor_sync(0xffffffffu, mx, off));
        float sum = 0.f;
        for (int kk = lane; kk < 65; kk += 32) sum += __expf(S[rr * 100 + kk] - mx);
#pragma unroll
        for (int off = 16; off; off >>= 1) sum += __shfl_xor_sync(0xffffffffu, sum, off);
        float inv = 1.0f / sum;
        for (int kk = lane; kk < 65; kk += 32)
            S[rr * 100 + kk] = __expf(S[rr * 100 + kk] - mx) * inv;
    }
    __syncthreads();

    // ---- A = fp16 hi/lo of softmax weights (cols 65..95 zero) ----
    for (int idx = tid; idx < 64 * 96; idx += 256) {
        int l = idx / 96, c = idx - l * 96;
        float v = (c < 65) ? S[l * 100 + c] : 0.f;
        __half hh = __float2half(v);
        *(__half*)(sm + AT_AH + (l * 104 + c) * 2) = hh;
        *(__half*)(sm + AT_AL + (l * 104 + c) * 2) = __float2half(v - __half2float(hh));
    }
    __syncthreads();

    // ---- O = A @ V (2-product) ----
    {
        const int n0w = warp_n * 32;
        float oacc[4][4];
#pragma unroll
        for (int na = 0; na < 4; na++)
#pragma unroll
            for (int q = 0; q < 4; q++) oacc[na][q] = 0.f;

#pragma unroll
        for (int ks = 0; ks < 6; ks++) {
            uint32_t ah4[4], al4[4], vh4[2][4];
            uint32_t aa = sb + AT_AH + (m0 + (g & 1) * 8 + r) * 208 + (g >> 1) * 16 + ks * 32;
            LDSM4(ah4, aa);
            LDSM4(al4, aa + (AT_AL - AT_AH));
#pragma unroll
            for (int p = 0; p < 2; p++) {
                uint32_t va = sb + AT_VH + (ks * 16 + (g & 1) * 8 + r) * 144
                              + (n0w + (g >> 1) * 8) * 2 + p * 32;
                LDSM4T(vh4[p], va);
            }
#pragma unroll
            for (int na = 0; na < 4; na++) {
                int p = na >> 1, q = (na & 1) * 2;
                MMA16816F16(oacc[na], ah4, vh4[p] + q);
                MMA16816F16(oacc[na], al4, vh4[p] + q);
            }
        }
        // write O as fp16 hi/lo
#pragma unroll
        for (int na = 0; na < 4; na++) {
            int d = n0w + na * 8 + (lane & 3) * 2;
            int l = m0 + (lane >> 2);
            size_t o0 = (bn * 64 + l) * 512 + h * 64 + d;
            size_t o1 = (bn * 64 + l + 8) * 512 + h * 64 + d;
            float v0 = oacc[na][0], v1 = oacc[na][1];
            float v2 = oacc[na][2], v3 = oacc[na][3];
            __half h0 = __float2half(v0), h1 = __float2half(v1);
            __half h2 = __float2half(v2), h3 = __float2half(v3);
            *(__half2*)&Ohg[o0] = __halves2half2(h0, h1);
            *(__half2*)&Ohg[o1] = __halves2half2(h2, h3);
            *(__half2*)&Olg[o0] = __halves2half2(__float2half(v0 - __half2float(h0)),
                                                 __float2half(v1 - __half2float(h1)));
            *(__half2*)&Olg[o1] = __halves2half2(__float2half(v2 - __half2float(h2)),
                                                 __float2half(v3 - __half2float(h3)));
        }
    }
}

// ================= launch =================
extern "C" void kernel_launch(void* const* d_in, const int* in_sizes, int n_in,
                              void* d_out, int out_size) {
    const float *x = 0, *edge = 0, *qkv_w = 0, *qkv_b = 0, *proj_w = 0, *proj_b = 0;
    const void  *mask = 0;
    for (int i = 0; i < n_in; i++) {
        switch (in_sizes[i]) {
            case 33554432: x      = (const float*)d_in[i]; break;
            case 1064960:  mask   = d_in[i];               break;
            case 4259840:  edge   = (const float*)d_in[i]; break;
            case 786432:   qkv_w  = (const float*)d_in[i]; break;
            case 1536:     qkv_b  = (const float*)d_in[i]; break;
            case 262144:   proj_w = (const float*)d_in[i]; break;
            case 512:      proj_b = (const float*)d_in[i]; break;
            default: break;
        }
    }
    float* out = (float*)d_out;

    __half *xh, *xl, *bmh, *bml, *wqh, *wph, *Qh, *Ql, *KVh, *KVl, *Oh, *Ol;
    cudaGetSymbolAddress((void**)&xh, g_xh);
    cudaGetSymbolAddress((void**)&xl, g_xl);
    cudaGetSymbolAddress((void**)&bmh, g_bmh);
    cudaGetSymbolAddress((void**)&bml, g_bml);
    cudaGetSymbolAddress((void**)&wqh, g_wqh);
    cudaGetSymbolAddress((void**)&wph, g_wph);
    cudaGetSymbolAddress((void**)&Qh, g_Qh);
    cudaGetSymbolAddress((void**)&Ql, g_Ql);
    cudaGetSymbolAddress((void**)&KVh, g_KVh);
    cudaGetSymbolAddress((void**)&KVl, g_KVl);
    cudaGetSymbolAddress((void**)&Oh, g_Oh);
    cudaGetSymbolAddress((void**)&Ol, g_Ol);

    cudaFuncSetAttribute(gemm_mma, cudaFuncAttributeMaxDynamicSharedMemorySize, GEMM_SMEM);
    cudaFuncSetAttribute(attn_mma, cudaFuncAttributeMaxDynamicSharedMemorySize, AT_SMEM);

    // 1. x -> fp16 hi/lo
    {
        size_t n = (size_t)BB * NBL * LQ * CC;
        split_kernel<<<(unsigned)((n + 255) / 256), 256>>>(x, xh, xl, n);
    }
    // 2. block means -> fp16 hi/lo
    block_mean_kernel<<<BB * NBL, CC>>>(x, bmh, bml);
    // 3. both weights -> fp16
    cvt_weights_kernel<<<(786432 + 262144 + 255) / 256, 256>>>(qkv_w, proj_w, wqh, wph);

    // 4. merged QKV GEMM -> Qh/Ql + KVh/KVl (fp16 hi/lo)
    gemm_mma<<<dim3(THREE_C / 128, 66560 / 128), 256, GEMM_SMEM>>>(
        xh, xl, bmh, bml, 1, wqh, THREE_C, qkv_b, 1, nullptr, 0, Qh, Ql, KVh, KVl);

    // 5. mask dtype detection
    detect_mask_kernel<<<1, 256>>>((const unsigned char*)mask);

    // 6. tensor-core attention -> Oh/Ol
    attn_mma<<<dim3(HH, NBL, BB), 256, AT_SMEM>>>(
        Qh, Ql, KVh, KVl, edge, mask, Oh, Ol);

    // 7. out = O @ Wp + bp
    gemm_mma<<<dim3(CC / 128, 65536 / 128), 256, GEMM_SMEM>>>(
        Oh, Ol, bmh, bml, 0, wph, CC, proj_b, 0, out, CC,
        nullptr, nullptr, nullptr, nullptr);
}

// round 14
// speedup vs baseline: 2.0238x; 1.0060x over previous
#include <cuda_runtime.h>
#include <cuda_bf16.h>
#include <cuda_fp16.h>
#include <cstdint>
#include <cstddef>

// Problem constants
#define BB   4
#define NBL  256
#define LQ   64
#define KK_  65
#define CC   512
#define HH   8
#define SCALE 0.125f
#define THREE_C 1536

// ---------------- scratch (static device globals: allocation-free) ----------------
__device__ __align__(128) __half g_xh[(size_t)BB * NBL * LQ * CC];
__device__ __align__(128) __half g_xl[(size_t)BB * NBL * LQ * CC];
__device__ __align__(128) __half g_bmh[(size_t)BB * NBL * CC];
__device__ __align__(128) __half g_bml[(size_t)BB * NBL * CC];
__device__ __align__(128) __half g_wqh[(size_t)CC * THREE_C];
__device__ __align__(128) __half g_wph[(size_t)CC * CC];
__device__ __align__(128) __half g_Qh[(size_t)BB * NBL * LQ * CC];
__device__ __align__(128) __half g_Ql[(size_t)BB * NBL * LQ * CC];
__device__ __align__(128) __half g_KVh[(size_t)BB * NBL * KK_ * 2 * CC];
__device__ __align__(128) __half g_KVl[(size_t)BB * NBL * KK_ * 2 * CC];
__device__ __align__(128) __half g_Oh[(size_t)BB * NBL * LQ * CC];
__device__ __align__(128) __half g_Ol[(size_t)BB * NBL * LQ * CC];
__device__ int g_mask_mode;

// ================= PTX helpers =================
__device__ __forceinline__ uint32_t smem_u32(const void* p) {
    uint32_t a;
    asm("{ .reg .u64 t; cvta.to.shared.u64 t, %1; cvt.u32.u64 %0, t; }" : "=r"(a) : "l"(p));
    return a;
}
#define CP16(d, s)   asm volatile("cp.async.cg.shared.global [%0], [%1], 16;" :: "r"(d), "l"(s))
#define CP_COMMIT()  asm volatile("cp.async.commit_group;" ::: "memory")
#define CP_WAIT2()   asm volatile("cp.async.wait_group 2;" ::: "memory")

#define LDSM4(d, addr)                                                           \
    asm volatile("ldmatrix.sync.aligned.m8n8.x4.shared.b16 {%0,%1,%2,%3}, [%4];" \
        : "=r"((d)[0]), "=r"((d)[1]), "=r"((d)[2]), "=r"((d)[3]) : "r"(addr))
#define LDSM4T(d, addr)                                                          \
    asm volatile("ldmatrix.sync.aligned.m8n8.x4.trans.shared.b16 {%0,%1,%2,%3}, [%4];" \
        : "=r"((d)[0]), "=r"((d)[1]), "=r"((d)[2]), "=r"((d)[3]) : "r"(addr))

#define MMA16816F16(acc, a, b)                                                   \
    asm volatile("mma.sync.aligned.m16n8k16.row.col.f32.f16.f16.f32 "            \
        "{%0,%1,%2,%3}, {%4,%5,%6,%7}, {%8,%9}, {%0,%1,%2,%3};"                  \
        : "+f"((acc)[0]), "+f"((acc)[1]), "+f"((acc)[2]), "+f"((acc)[3])         \
        : "r"((a)[0]), "r"((a)[1]), "r"((a)[2]), "r"((a)[3]),                    \
          "r"((b)[0]), "r"((b)[1]))

// ================= small kernels =================
__global__ void detect_mask_kernel(const unsigned char* __restrict__ m) {
    __shared__ int sA, s0;
    if (threadIdx.x == 0) { sA = 0; s0 = 0; }
    __syncthreads();
    int a = 0, z = 0;
    for (int i = threadIdx.x; i < 4096; i += blockDim.x) {
        int v = m[i];
        if ((i & 3) == 1) a |= v;
        if ((i & 3) == 0) z |= v;
    }
    if (a) atomicOr(&sA, 1);
    if (z) atomicOr(&s0, 1);
    __syncthreads();
    if (threadIdx.x == 0) g_mask_mode = sA ? 0 : (s0 ? 1 : 2);
}

__global__ void block_mean_kernel(const float* __restrict__ x,
                                  __half* __restrict__ bmh, __half* __restrict__ bml) {
    int blk = blockIdx.x, c = threadIdx.x;
    const float* base = x + (size_t)blk * LQ * CC + c;
    float s = 0.f;
#pragma unroll
    for (int l = 0; l < LQ; l++) s += base[(size_t)l * CC];
    float m = s * (1.0f / 64.0f);
    __half h = __float2half(m);
    bmh[(size_t)blk * CC + c] = h;
    bml[(size_t)blk * CC + c] = __float2half(m - __half2float(h));
}

__global__ void split_kernel(const float* __restrict__ src,
                             __half* __restrict__ dh,
                             __half* __restrict__ dl, size_t n) {
    size_t i = (size_t)blockIdx.x * blockDim.x + threadIdx.x;
    if (i >= n) return;
    float v = src[i];
    __half h = __float2half(v);
    dh[i] = h;
    dl[i] = __float2half(v - __half2float(h));
}

__global__ void cvt_weights_kernel(const float* __restrict__ wq,
                                   const float* __restrict__ wp,
                                   __half* __restrict__ wqh, __half* __restrict__ wph) {
    size_t i = (size_t)blockIdx.x * blockDim.x + threadIdx.x;
    const size_t n1 = (size_t)CC * THREE_C;
    const size_t n2 = (size_t)CC * CC;
    if (i < n1) wqh[i] = __float2half(wq[i]);
    else if (i < n1 + n2) wph[i - n1] = __float2half(wp[i - n1]);
}

// ================= mma.sync fp16 GEMM (2-product compensation) =================
#define KCHUNK     32
#define NCHUNK     16
#define A_STRIDE_B 80
#define B_STRIDE_B 272
#define A_HALF     10240
#define B_OFF      20480
#define STAGE_BYTES 29184
#define GEMM_SMEM  (3 * STAGE_BYTES)

__device__ __forceinline__ void a_ptrs(
    const __half* __restrict__ Ah, const __half* __restrict__ Al,
    const __half* __restrict__ bmh, const __half* __restrict__ bml,
    int gmode, int gr,
    const __half*& ph, const __half*& pl)
{
    if (gmode == 0) { size_t o = (size_t)gr * CC; ph = Ah + o; pl = Al + o; return; }
    int b  = gr / (NBL * KK_);
    int t  = gr - b * (NBL * KK_);
    int nb = t / KK_;
    int kk = t - nb * KK_;
    if (kk < LQ) { size_t o = ((size_t)(b * NBL + nb) * LQ + kk) * CC; ph = Ah + o; pl = Al + o; }
    else         { size_t o = (size_t)(b * NBL + nb) * CC;             ph = bmh + o; pl = bml + o; }
}

__global__ __launch_bounds__(256) void gemm_mma(
    const __half* __restrict__ Ah, const __half* __restrict__ Al,
    const __half* __restrict__ bmh, const __half* __restrict__ bml,
    int gmode,
    const __half* __restrict__ Bh, int ldB,
    const float* __restrict__ bias,
    int epi_mode,
    float* __restrict__ C, int ldc,
    __half* __restrict__ QhP, __half* __restrict__ QlP,
    __half* __restrict__ KVhP, __half* __restrict__ KVlP)
{
    extern __shared__ __align__(128) char smem[];
    const uint32_t sb = smem_u32(smem);
    const int tid = threadIdx.x, wid = tid >> 5, lane = tid & 31;
    const int warp_m = wid >> 2, warp_n = wid & 3;
    const int rowBase = blockIdx.y * 128;
    const int colBase = blockIdx.x * 128;
    const int g = lane >> 3, r = lane & 7;

    float acc[4][4][4];
#pragma unroll
    for (int ma = 0; ma < 4; ma++)
#pragma unroll
        for (int na = 0; na < 4; na++)
#pragma unroll
            for (int q = 0; q < 4; q++) acc[ma][na][q] = 0.f;

    const uint32_t aOff = (uint32_t)((warp_m * 64 + (g & 1) * 8 + r) * A_STRIDE_B + (g >> 1) * 16);
    const uint32_t bOff = (uint32_t)(B_OFF + ((g & 1) * 8 + r) * B_STRIDE_B
                                     + (warp_n * 32 + (g >> 1) * 8) * 2);

    auto load_chunk = [&](int k0, uint32_t stBase) {
#pragma unroll
        for (int i = tid; i < 512; i += 256) {
            int row = i >> 2, seg = i & 3;
            const __half *ph, *pl;
            a_ptrs(Ah, Al, bmh, bml, gmode, rowBase + row, ph, pl);
            uint32_t da = stBase + row * A_STRIDE_B + seg * 16;
            CP16(da,          ph + k0 + seg * 8);
            CP16(da + A_HALF, pl + k0 + seg * 8);
        }
#pragma unroll
        for (int i = tid; i < 512; i += 256) {
            int row = i >> 4, seg = i & 15;
            size_t off = (size_t)(k0 + row) * ldB + colBase + seg * 8;
            CP16(stBase + B_OFF + row * B_STRIDE_B + seg * 16, Bh + off);
        }
    };

#pragma unroll
    for (int s = 0; s < 3; s++) {
        load_chunk(s * KCHUNK, sb + s * STAGE_BYTES);
        CP_COMMIT();
    }

    for (int c = 0; c < NCHUNK; c++) {
        CP_WAIT2();
        __syncthreads();
        const uint32_t st = sb + (c % 3) * STAGE_BYTES;

#pragma unroll
        for (int ks = 0; ks < 2; ks++) {
            uint32_t ah[4][4], al[4][4], bh[2][4];
#pragma unroll
            for (int ma = 0; ma < 4; ma++) {
                uint32_t ad = st + aOff + ma * (16 * A_STRIDE_B) + ks * 32;
                LDSM4(ah[ma], ad);
                LDSM4(al[ma], ad + A_HALF);
            }
#pragma unroll
            for (int p = 0; p < 2; p++) {
                uint32_t bd = st + bOff + ks * (16 * B_STRIDE_B) + p * 32;
                LDSM4T(bh[p], bd);
            }
#pragma unroll
            for (int ma = 0; ma < 4; ma++)
#pragma unroll
                for (int na = 0; na < 4; na++) {
                    int p = na >> 1, q = (na & 1) * 2;
                    MMA16816F16(acc[ma][na], ah[ma], bh[p] + q);
                    MMA16816F16(acc[ma][na], al[ma], bh[p] + q);
                }
        }
        __syncthreads();
        if (c + 3 < NCHUNK) load_chunk((c + 3) * KCHUNK, st);
        CP_COMMIT();
    }

    // ---- epilogue ----
    if (epi_mode == 0) {
#pragma unroll
        for (int ma = 0; ma < 4; ma++) {
            int gr = rowBase + warp_m * 64 + ma * 16 + (lane >> 2);
#pragma unroll
            for (int na = 0; na < 4; na++) {
                int gc = colBase + warp_n * 32 + na * 8 + 2 * (lane & 3);
                float b0 = bias[gc], b1 = bias[gc + 1];
                float2 v0 = make_float2(acc[ma][na][0] + b0, acc[ma][na][1] + b1);
                float2 v1 = make_float2(acc[ma][na][2] + b0, acc[ma][na][3] + b1);
                *(float2*)&C[(size_t)gr * ldc + gc]       = v0;
                *(float2*)&C[(size_t)(gr + 8) * ldc + gc] = v1;
            }
        }
    } else {
        const bool isQ = (colBase < 512);
#pragma unroll
        for (int ma = 0; ma < 4; ma++) {
            int gr0 = rowBase + warp_m * 64 + ma * 16 + (lane >> 2);
#pragma unroll
            for (int rr = 0; rr < 2; rr++) {
                int gr = gr0 + rr * 8;
                int b  = gr / (NBL * KK_);
                int t  = gr - b * (NBL * KK_);
                int nb = t / KK_;
                int kk = t - nb * KK_;
                size_t bn = (size_t)b * NBL + nb;
                __half *dh, *dl;
                int cshift;
                if (isQ) {
                    if (kk >= LQ) continue;
                    size_t o = (bn * 64 + kk) * 512;
                    dh = QhP + o; dl = QlP + o; cshift = 0;
                } else {
                    size_t o = (bn * 65 + kk) * 1024;
                    dh = KVhP + o; dl = KVlP + o; cshift = 512;
                }
#pragma unroll
                for (int na = 0; na < 4; na++) {
                    int gc = colBase + warp_n * 32 + na * 8 + 2 * (lane & 3);
                    float v0 = acc[ma][na][rr * 2]     + bias[gc];
                    float v1 = acc[ma][na][rr * 2 + 1] + bias[gc + 1];
                    __half h0 = __float2half(v0), h1 = __float2half(v1);
                    __half l0 = __float2half(v0 - __half2float(h0));
                    __half l1 = __float2half(v1 - __half2float(h1));
                    int cc = gc - cshift;
                    *(__half2*)&dh[cc] = __halves2half2(h0, h1);
                    *(__half2*)&dl[cc] = __halves2half2(l0, l1);
                }
            }
        }
    }
}

// ================= mma.sync attention per (b,nb,h) ==========================
// K padded to 80 rows. Scores: (Qh,Ql)x(Kh,Kl) 3-product over 80 cols
// (warp_n=0: cols 0-47, warp_n=1: cols 48-79). AV: Ah x Vh 1-product, k=80.
// smem byte offsets: Q rows 64 stride 144B; K/V rows 80 stride 144B;
// S fp32 stride 100; A fp16 stride 104 halves.
#define AT_QH 0
#define AT_QL 9216
#define AT_KH 18432
#define AT_KL 29952
#define AT_VH 41472
#define AT_SS 52992
#define AT_AH 78592
#define AT_SMEM 91904

__global__ __launch_bounds__(256) void attn_mma(
    const __half* __restrict__ Qhg, const __half* __restrict__ Qlg,
    const __half* __restrict__ KVhg, const __half* __restrict__ KVlg,
    const float* __restrict__ edge, const void* __restrict__ maskp,
    __half* __restrict__ Ohg, __half* __restrict__ Olg)
{
    extern __shared__ __align__(128) char sm[];
    const uint32_t sb = smem_u32(sm);
    float* S = (float*)(sm + AT_SS);

    const int h  = blockIdx.x;
    const int nb = blockIdx.y;
    const int b  = blockIdx.z;
    const int tid = threadIdx.x, wid = tid >> 5, lane = tid & 31;
    const int g = lane >> 3, r = lane & 7;
    const size_t bn = (size_t)b * NBL + nb;

    // ---- load Q (64x64) and K/V (65x64 + zero pad to 80 rows) ----
    for (int i = tid; i < 512; i += 256) {
        int row = i >> 3, ch = i & 7;
        size_t go = (bn * 64 + row) * 512 + h * 64 + ch * 8;
        *(uint4*)(sm + AT_QH + row * 144 + ch * 16) = *(const uint4*)&Qhg[go];
        *(uint4*)(sm + AT_QL + row * 144 + ch * 16) = *(const uint4*)&Qlg[go];
    }
    for (int i = tid; i < 640; i += 256) {
        int row = i >> 3, ch = i & 7;
        uint4 kh = {0,0,0,0}, kl = {0,0,0,0}, vh = {0,0,0,0};
        if (row < 65) {
            size_t go = (bn * 65 + row) * 1024 + h * 64 + ch * 8;
            kh = *(const uint4*)&KVhg[go];
            kl = *(const uint4*)&KVlg[go];
            vh = *(const uint4*)&KVhg[go + 512];
        }
        *(uint4*)(sm + AT_KH + row * 144 + ch * 16) = kh;
        *(uint4*)(sm + AT_KL + row * 144 + ch * 16) = kl;
        *(uint4*)(sm + AT_VH + row * 144 + ch * 16) = vh;
    }
    __syncthreads();

    // ---- scores: S[64][80] = Q @ K^T (3-product) ----
    const int warp_m = wid & 3, warp_n = wid >> 2;
    const int m0 = warp_m * 16, n0 = warp_n * 48;
    const int ntc = warp_n ? 2 : 3;       // warp_n0: cols 0-47, warp_n1: 48-79
    {
        float sacc[3][8];                  // [ktile][2 ntiles interleaved? no: [t][oquad]]
        // layout: sacc[t][o*4..o*4+3] for sub-tile (t, o)
#pragma unroll
        for (int t = 0; t < 3; t++)
#pragma unroll
            for (int q = 0; q < 8; q++) sacc[t][q] = 0.f;

#pragma unroll
        for (int ks = 0; ks < 4; ks++) {
            uint32_t qh4[4], ql4[4], kh4[3][4], kl4[3][4];
            uint32_t qa = sb + AT_QH + (m0 + (g & 1) * 8 + r) * 144 + (g >> 1) * 16 + ks * 32;
            LDSM4(qh4, qa);
            LDSM4(ql4, qa + (AT_QL - AT_QH));
#pragma unroll
            for (int t = 0; t < 3; t++) {
                if (t < ntc) {
                    uint32_t ka = sb + AT_KH + (n0 + t * 16 + (g & 1) * 8 + r) * 144
                                  + (g >> 1) * 16 + ks * 32;
                    LDSM4(kh4[t], ka);
                    LDSM4(kl4[t], ka + (AT_KL - AT_KH));
                }
            }
#pragma unroll
            for (int t = 0; t < 3; t++) {
                if (t < ntc) {
#pragma unroll
                    for (int o = 0; o < 2; o++) {
                        uint32_t bfh[2] = { kh4[t][o], kh4[t][o + 2] };
                        uint32_t bfl[2] = { kl4[t][o], kl4[t][o + 2] };
                        MMA16816F16(sacc[t] + o * 4, qh4, bfh);
                        MMA16816F16(sacc[t] + o * 4, ql4, bfh);
                        MMA16816F16(sacc[t] + o * 4, qh4, bfl);
                    }
                }
            }
        }
#pragma unroll
        for (int t = 0; t < 3; t++) {
            if (t < ntc) {
#pragma unroll
                for (int o = 0; o < 2; o++) {
                    int col = n0 + t * 16 + o * 8 + (lane & 3) * 2;
                    int row = m0 + (lane >> 2);
                    *(float2*)&S[row * 100 + col] =
                        make_float2(sacc[t][o * 4], sacc[t][o * 4 + 1]);
                    *(float2*)&S[(row + 8) * 100 + col] =
                        make_float2(sacc[t][o * 4 + 2], sacc[t][o * 4 + 3]);
                }
            }
        }
    }
    __syncthreads();

    // ---- scale + bias + mask (cols < 65) ----
    const int mode = g_mask_mode;
    for (int idx = tid; idx < 64 * 65; idx += 256) {
        int l  = idx / 65;
        int kk = idx - l * 65;
        float s = S[l * 100 + kk] * SCALE;
        float bias;
        if (kk == 64 || kk == l) bias = 1.0f;
        else bias = edge[((((size_t)nb * 64) + l) * 65 + kk) * 4 + 3];
        s += bias;
        size_t mi = ((size_t)nb * 64 + l) * 65 + kk;
        bool ok;
        if (mode == 0)      ok = ((const unsigned char*)maskp)[mi] != 0;
        else if (mode == 1) ok = ((const int*)maskp)[mi] != 0;
        else                ok = ((const float*)maskp)[mi] != 0.0f;
        S[l * 100 + kk] = ok ? s : -1.0e9f;
    }
    __syncthreads();

    // ---- softmax rows (cols < 65) ----
    for (int rr = wid; rr < 64; rr += 8) {
        float mx = -1.0e30f;
        for (int kk = lane; kk < 65; kk += 32) mx = fmaxf(mx, S[rr * 100 + kk]);
#pragma unroll
        for (int off = 16; off; off >>= 1) mx = fmaxf(mx, __shfl_xor_sync(0xffffffffu, mx, off));
        float sum = 0.f;
        for (int kk = lane; kk < 65; kk += 32) sum += __expf(S[rr * 100 + kk] - mx);
#pragma unroll
        for (int off = 16; off; off >>= 1) sum += __shfl_xor_sync(0xffffffffu, sum, off);
        float inv = 1.0f / sum;
        for (int kk = lane; kk < 65; kk += 32)
            S[rr * 100 + kk] = __expf(S[rr * 100 + kk] - mx) * inv;
    }
    __syncthreads();

    // ---- A = fp16 of softmax weights (cols 65..79 zero), 1-product AV ----
    for (int idx = tid; idx < 64 * 80; idx += 256) {
        int l = idx / 80, c = idx - l * 80;
        float v = (c < 65) ? S[l * 100 + c] : 0.f;
        *(__half*)(sm + AT_AH + (l * 104 + c) * 2) = __float2half(v);
    }
    __syncthreads();

    // ---- O = A @ V ----
    {
        const int n0w = warp_n * 32;
        float oacc[4][4];
#pragma unroll
        for (int na = 0; na < 4; na++)
#pragma unroll
            for (int q = 0; q < 4; q++) oacc[na][q] = 0.f;

#pragma unroll
        for (int ks = 0; ks < 5; ks++) {
            uint32_t ah4[4], vh4[2][4];
            uint32_t aa = sb + AT_AH + (m0 + (g & 1) * 8 + r) * 208 + (g >> 1) * 16 + ks * 32;
            LDSM4(ah4, aa);
#pragma unroll
            for (int p = 0; p < 2; p++) {
                uint32_t va = sb + AT_VH + (ks * 16 + (g & 1) * 8 + r) * 144
                              + (n0w + (g >> 1) * 8) * 2 + p * 32;
                LDSM4T(vh4[p], va);
            }
#pragma unroll
            for (int na = 0; na < 4; na++) {
                int p = na >> 1, q = (na & 1) * 2;
                MMA16816F16(oacc[na], ah4, vh4[p] + q);
            }
        }
        // write O as fp16 hi/lo
#pragma unroll
        for (int na = 0; na < 4; na++) {
            int d = n0w + na * 8 + (lane & 3) * 2;
            int l = m0 + (lane >> 2);
            size_t o0 = (bn * 64 + l) * 512 + h * 64 + d;
            size_t o1 = (bn * 64 + l + 8) * 512 + h * 64 + d;
            float v0 = oacc[na][0], v1 = oacc[na][1];
            float v2 = oacc[na][2], v3 = oacc[na][3];
            __half h0 = __float2half(v0), h1 = __float2half(v1);
            __half h2 = __float2half(v2), h3 = __float2half(v3);
            *(__half2*)&Ohg[o0] = __halves2half2(h0, h1);
            *(__half2*)&Ohg[o1] = __halves2half2(h2, h3);
            *(__half2*)&Olg[o0] = __halves2half2(__float2half(v0 - __half2float(h0)),
                                                 __float2half(v1 - __half2float(h1)));
            *(__half2*)&Olg[o1] = __halves2half2(__float2half(v2 - __half2float(h2)),
                                                 __float2half(v3 - __half2float(h3)));
        }
    }
}

// ================= launch =================
extern "C" void kernel_launch(void* const* d_in, const int* in_sizes, int n_in,
                              void* d_out, int out_size) {
    const float *x = 0, *edge = 0, *qkv_w = 0, *qkv_b = 0, *proj_w = 0, *proj_b = 0;
    const void  *mask = 0;
    for (int i = 0; i < n_in; i++) {
        switch (in_sizes[i]) {
            case 33554432: x      = (const float*)d_in[i]; break;
            case 1064960:  mask   = d_in[i];               break;
            case 4259840:  edge   = (const float*)d_in[i]; break;
            case 786432:   qkv_w  = (const float*)d_in[i]; break;
            case 1536:     qkv_b  = (const float*)d_in[i]; break;
            case 262144:   proj_w = (const float*)d_in[i]; break;
            case 512:      proj_b = (const float*)d_in[i]; break;
            default: break;
        }
    }
    float* out = (float*)d_out;

    __half *xh, *xl, *bmh, *bml, *wqh, *wph, *Qh, *Ql, *KVh, *KVl, *Oh, *Ol;
    cudaGetSymbolAddress((void**)&xh, g_xh);
    cudaGetSymbolAddress((void**)&xl, g_xl);
    cudaGetSymbolAddress((void**)&bmh, g_bmh);
    cudaGetSymbolAddress((void**)&bml, g_bml);
    cudaGetSymbolAddress((void**)&wqh, g_wqh);
    cudaGetSymbolAddress((void**)&wph, g_wph);
    cudaGetSymbolAddress((void**)&Qh, g_Qh);
    cudaGetSymbolAddress((void**)&Ql, g_Ql);
    cudaGetSymbolAddress((void**)&KVh, g_KVh);
    cudaGetSymbolAddress((void**)&KVl, g_KVl);
    cudaGetSymbolAddress((void**)&Oh, g_Oh);
    cudaGetSymbolAddress((void**)&Ol, g_Ol);

    cudaFuncSetAttribute(gemm_mma, cudaFuncAttributeMaxDynamicSharedMemorySize, GEMM_SMEM);
    cudaFuncSetAttribute(attn_mma, cudaFuncAttributeMaxDynamicSharedMemorySize, AT_SMEM);

    // 1. x -> fp16 hi/lo
    {
        size_t n = (size_t)BB * NBL * LQ * CC;
        split_kernel<<<(unsigned)((n + 255) / 256), 256>>>(x, xh, xl, n);
    }
    // 2. block means -> fp16 hi/lo
    block_mean_kernel<<<BB * NBL, CC>>>(x, bmh, bml);
    // 3. both weights -> fp16
    cvt_weights_kernel<<<(786432 + 262144 + 255) / 256, 256>>>(qkv_w, proj_w, wqh, wph);

    // 4. merged QKV GEMM -> Qh/Ql + KVh/KVl (fp16 hi/lo)
    gemm_mma<<<dim3(THREE_C / 128, 66560 / 128), 256, GEMM_SMEM>>>(
        xh, xl, bmh, bml, 1, wqh, THREE_C, qkv_b, 1, nullptr, 0, Qh, Ql, KVh, KVl);

    // 5. mask dtype detection
    detect_mask_kernel<<<1, 256>>>((const unsigned char*)mask);

    // 6. tensor-core attention -> Oh/Ol
    attn_mma<<<dim3(HH, NBL, BB), 256, AT_SMEM>>>(
        Qh, Ql, KVh, KVl, edge, mask, Oh, Ol);

    // 7. out = O @ Wp + bp
    gemm_mma<<<dim3(CC / 128, 65536 / 128), 256, GEMM_SMEM>>>(
        Oh, Ol, bmh, bml, 0, wph, CC, proj_b, 0, out, CC,
        nullptr, nullptr, nullptr, nullptr);
}

// round 16
// speedup vs baseline: 2.1236x; 1.0493x over previous
#include <cuda_runtime.h>
#include <cuda_bf16.h>
#include <cuda_fp16.h>
#include <cstdint>
#include <cstddef>

// Problem constants
#define BB   4
#define NBL  256
#define LQ   64
#define KK_  65
#define CC   512
#define HH   8
#define SCALE 0.125f
#define THREE_C 1536

// ---------------- scratch (static device globals: allocation-free) ----------------
__device__ __align__(128) __half g_xh[(size_t)BB * NBL * LQ * CC];
__device__ __align__(128) __half g_xl[(size_t)BB * NBL * LQ * CC];
__device__ __align__(128) __half g_bmh[(size_t)BB * NBL * CC];
__device__ __align__(128) __half g_bml[(size_t)BB * NBL * CC];
__device__ __align__(128) __half g_wqh[(size_t)CC * THREE_C];
__device__ __align__(128) __half g_wph[(size_t)CC * CC];
__device__ __align__(128) __half g_Qh[(size_t)BB * NBL * LQ * CC];
__device__ __align__(128) __half g_Ql[(size_t)BB * NBL * LQ * CC];
__device__ __align__(128) __half g_KVh[(size_t)BB * NBL * KK_ * 2 * CC];
__device__ __align__(128) __half g_KVl[(size_t)BB * NBL * KK_ * 2 * CC];
__device__ __align__(128) __half g_Oh[(size_t)BB * NBL * LQ * CC];
__device__ __align__(128) __half g_Ol[(size_t)BB * NBL * LQ * CC];
__device__ int g_mask_mode;

// ================= PTX helpers =================
__device__ __forceinline__ uint32_t smem_u32(const void* p) {
    uint32_t a;
    asm("{ .reg .u64 t; cvta.to.shared.u64 t, %1; cvt.u32.u64 %0, t; }" : "=r"(a) : "l"(p));
    return a;
}
#define CP16(d, s)   asm volatile("cp.async.cg.shared.global [%0], [%1], 16;" :: "r"(d), "l"(s))
#define CP_COMMIT()  asm volatile("cp.async.commit_group;" ::: "memory")
#define CP_WAIT2()   asm volatile("cp.async.wait_group 2;" ::: "memory")

#define LDSM4(d, addr)                                                           \
    asm volatile("ldmatrix.sync.aligned.m8n8.x4.shared.b16 {%0,%1,%2,%3}, [%4];" \
        : "=r"((d)[0]), "=r"((d)[1]), "=r"((d)[2]), "=r"((d)[3]) : "r"(addr))
#define LDSM4T(d, addr)                                                          \
    asm volatile("ldmatrix.sync.aligned.m8n8.x4.trans.shared.b16 {%0,%1,%2,%3}, [%4];" \
        : "=r"((d)[0]), "=r"((d)[1]), "=r"((d)[2]), "=r"((d)[3]) : "r"(addr))

#define MMA16816F16(acc, a, b)                                                   \
    asm volatile("mma.sync.aligned.m16n8k16.row.col.f32.f16.f16.f32 "            \
        "{%0,%1,%2,%3}, {%4,%5,%6,%7}, {%8,%9}, {%0,%1,%2,%3};"                  \
        : "+f"((acc)[0]), "+f"((acc)[1]), "+f"((acc)[2]), "+f"((acc)[3])         \
        : "r"((a)[0]), "r"((a)[1]), "r"((a)[2]), "r"((a)[3]),                    \
          "r"((b)[0]), "r"((b)[1]))

// ================= small kernels =================
__global__ void detect_mask_kernel(const unsigned char* __restrict__ m) {
    __shared__ int sA, s0;
    if (threadIdx.x == 0) { sA = 0; s0 = 0; }
    __syncthreads();
    int a = 0, z = 0;
    for (int i = threadIdx.x; i < 4096; i += blockDim.x) {
        int v = m[i];
        if ((i & 3) == 1) a |= v;
        if ((i & 3) == 0) z |= v;
    }
    if (a) atomicOr(&sA, 1);
    if (z) atomicOr(&s0, 1);
    __syncthreads();
    if (threadIdx.x == 0) g_mask_mode = sA ? 0 : (s0 ? 1 : 2);
}

__global__ void block_mean_kernel(const float* __restrict__ x,
                                  __half* __restrict__ bmh, __half* __restrict__ bml) {
    int blk = blockIdx.x, c = threadIdx.x;
    const float* base = x + (size_t)blk * LQ * CC + c;
    float s = 0.f;
#pragma unroll
    for (int l = 0; l < LQ; l++) s += base[(size_t)l * CC];
    float m = s * (1.0f / 64.0f);
    __half h = __float2half(m);
    bmh[(size_t)blk * CC + c] = h;
    bml[(size_t)blk * CC + c] = __float2half(m - __half2float(h));
}

__global__ void split_kernel(const float* __restrict__ src,
                             __half* __restrict__ dh,
                             __half* __restrict__ dl, size_t n) {
    size_t i = (size_t)blockIdx.x * blockDim.x + threadIdx.x;
    if (i >= n) return;
    float v = src[i];
    __half h = __float2half(v);
    dh[i] = h;
    dl[i] = __float2half(v - __half2float(h));
}

__global__ void cvt_weights_kernel(const float* __restrict__ wq,
                                   const float* __restrict__ wp,
                                   __half* __restrict__ wqh, __half* __restrict__ wph) {
    size_t i = (size_t)blockIdx.x * blockDim.x + threadIdx.x;
    const size_t n1 = (size_t)CC * THREE_C;
    const size_t n2 = (size_t)CC * CC;
    if (i < n1) wqh[i] = __float2half(wq[i]);
    else if (i < n1 + n2) wph[i - n1] = __float2half(wp[i - n1]);
}

// ================= mma.sync fp16 GEMM (2-product compensation) =================
#define KCHUNK     32
#define NCHUNK     16
#define A_STRIDE_B 80
#define B_STRIDE_B 272
#define A_HALF     10240
#define B_OFF      20480
#define STAGE_BYTES 29184
#define GEMM_SMEM  (3 * STAGE_BYTES)

__device__ __forceinline__ void a_ptrs(
    const __half* __restrict__ Ah, const __half* __restrict__ Al,
    const __half* __restrict__ bmh, const __half* __restrict__ bml,
    int gmode, int gr,
    const __half*& ph, const __half*& pl)
{
    if (gmode == 0) { size_t o = (size_t)gr * CC; ph = Ah + o; pl = Al + o; return; }
    int b  = gr / (NBL * KK_);
    int t  = gr - b * (NBL * KK_);
    int nb = t / KK_;
    int kk = t - nb * KK_;
    if (kk < LQ) { size_t o = ((size_t)(b * NBL + nb) * LQ + kk) * CC; ph = Ah + o; pl = Al + o; }
    else         { size_t o = (size_t)(b * NBL + nb) * CC;             ph = bmh + o; pl = bml + o; }
}

__global__ __launch_bounds__(256) void gemm_mma(
    const __half* __restrict__ Ah, const __half* __restrict__ Al,
    const __half* __restrict__ bmh, const __half* __restrict__ bml,
    int gmode,
    const __half* __restrict__ Bh, int ldB,
    const float* __restrict__ bias,
    int epi_mode,
    float* __restrict__ C, int ldc,
    __half* __restrict__ QhP, __half* __restrict__ QlP,
    __half* __restrict__ KVhP, __half* __restrict__ KVlP)
{
    extern __shared__ __align__(128) char smem[];
    const uint32_t sb = smem_u32(smem);
    const int tid = threadIdx.x, wid = tid >> 5, lane = tid & 31;
    const int warp_m = wid >> 2, warp_n = wid & 3;
    const int rowBase = blockIdx.y * 128;
    const int colBase = blockIdx.x * 128;
    const int g = lane >> 3, r = lane & 7;

    float acc[4][4][4];
#pragma unroll
    for (int ma = 0; ma < 4; ma++)
#pragma unroll
        for (int na = 0; na < 4; na++)
#pragma unroll
            for (int q = 0; q < 4; q++) acc[ma][na][q] = 0.f;

    const uint32_t aOff = (uint32_t)((warp_m * 64 + (g & 1) * 8 + r) * A_STRIDE_B + (g >> 1) * 16);
    const uint32_t bOff = (uint32_t)(B_OFF + ((g & 1) * 8 + r) * B_STRIDE_B
                                     + (warp_n * 32 + (g >> 1) * 8) * 2);

    auto load_chunk = [&](int k0, uint32_t stBase) {
#pragma unroll
        for (int i = tid; i < 512; i += 256) {
            int row = i >> 2, seg = i & 3;
            const __half *ph, *pl;
            a_ptrs(Ah, Al, bmh, bml, gmode, rowBase + row, ph, pl);
            uint32_t da = stBase + row * A_STRIDE_B + seg * 16;
            CP16(da,          ph + k0 + seg * 8);
            CP16(da + A_HALF, pl + k0 + seg * 8);
        }
#pragma unroll
        for (int i = tid; i < 512; i += 256) {
            int row = i >> 4, seg = i & 15;
            size_t off = (size_t)(k0 + row) * ldB + colBase + seg * 8;
            CP16(stBase + B_OFF + row * B_STRIDE_B + seg * 16, Bh + off);
        }
    };

#pragma unroll
    for (int s = 0; s < 3; s++) {
        load_chunk(s * KCHUNK, sb + s * STAGE_BYTES);
        CP_COMMIT();
    }

    for (int c = 0; c < NCHUNK; c++) {
        CP_WAIT2();
        __syncthreads();
        const uint32_t st = sb + (c % 3) * STAGE_BYTES;

#pragma unroll
        for (int ks = 0; ks < 2; ks++) {
            uint32_t ah[4][4], al[4][4], bh[2][4];
#pragma unroll
            for (int ma = 0; ma < 4; ma++) {
                uint32_t ad = st + aOff + ma * (16 * A_STRIDE_B) + ks * 32;
                LDSM4(ah[ma], ad);
                LDSM4(al[ma], ad + A_HALF);
            }
#pragma unroll
            for (int p = 0; p < 2; p++) {
                uint32_t bd = st + bOff + ks * (16 * B_STRIDE_B) + p * 32;
                LDSM4T(bh[p], bd);
            }
#pragma unroll
            for (int ma = 0; ma < 4; ma++)
#pragma unroll
                for (int na = 0; na < 4; na++) {
                    int p = na >> 1, q = (na & 1) * 2;
                    MMA16816F16(acc[ma][na], ah[ma], bh[p] + q);
                    MMA16816F16(acc[ma][na], al[ma], bh[p] + q);
                }
        }
        __syncthreads();
        if (c + 3 < NCHUNK) load_chunk((c + 3) * KCHUNK, st);
        CP_COMMIT();
    }

    // ---- epilogue ----
    if (epi_mode == 0) {
#pragma unroll
        for (int ma = 0; ma < 4; ma++) {
            int gr = rowBase + warp_m * 64 + ma * 16 + (lane >> 2);
#pragma unroll
            for (int na = 0; na < 4; na++) {
                int gc = colBase + warp_n * 32 + na * 8 + 2 * (lane & 3);
                float b0 = bias[gc], b1 = bias[gc + 1];
                float2 v0 = make_float2(acc[ma][na][0] + b0, acc[ma][na][1] + b1);
                float2 v1 = make_float2(acc[ma][na][2] + b0, acc[ma][na][3] + b1);
                *(float2*)&C[(size_t)gr * ldc + gc]       = v0;
                *(float2*)&C[(size_t)(gr + 8) * ldc + gc] = v1;
            }
        }
    } else {
        const bool isQ = (colBase < 512);
#pragma unroll
        for (int ma = 0; ma < 4; ma++) {
            int gr0 = rowBase + warp_m * 64 + ma * 16 + (lane >> 2);
#pragma unroll
            for (int rr = 0; rr < 2; rr++) {
                int gr = gr0 + rr * 8;
                int b  = gr / (NBL * KK_);
                int t  = gr - b * (NBL * KK_);
                int nb = t / KK_;
                int kk = t - nb * KK_;
                size_t bn = (size_t)b * NBL + nb;
                __half *dh, *dl;
                int cshift;
                if (isQ) {
                    if (kk >= LQ) continue;
                    size_t o = (bn * 64 + kk) * 512;
                    dh = QhP + o; dl = QlP + o; cshift = 0;
                } else {
                    size_t o = (bn * 65 + kk) * 1024;
                    dh = KVhP + o; dl = KVlP + o; cshift = 512;
                }
#pragma unroll
                for (int na = 0; na < 4; na++) {
                    int gc = colBase + warp_n * 32 + na * 8 + 2 * (lane & 3);
                    float v0 = acc[ma][na][rr * 2]     + bias[gc];
                    float v1 = acc[ma][na][rr * 2 + 1] + bias[gc + 1];
                    __half h0 = __float2half(v0), h1 = __float2half(v1);
                    __half l0 = __float2half(v0 - __half2float(h0));
                    __half l1 = __float2half(v1 - __half2float(h1));
                    int cc = gc - cshift;
                    *(__half2*)&dh[cc] = __halves2half2(h0, h1);
                    *(__half2*)&dl[cc] = __halves2half2(l0, l1);
                }
            }
        }
    }
}

// ================= mma.sync attention per (b,nb,h) ==========================
// K padded to 80 rows. Scores 3-product; AV 1-product.
// Softmax: no max-shift (scores bounded ~|15| << 88; masked -1e9 -> exp = 0),
// ONE __expf per element, A-matrix fp16 conversion fused into normalize pass.
#define AT_QH 0
#define AT_QL 9216
#define AT_KH 18432
#define AT_KL 29952
#define AT_VH 41472
#define AT_SS 52992
#define AT_AH 78592
#define AT_SMEM 91904

__global__ __launch_bounds__(256) void attn_mma(
    const __half* __restrict__ Qhg, const __half* __restrict__ Qlg,
    const __half* __restrict__ KVhg, const __half* __restrict__ KVlg,
    const float* __restrict__ edge, const void* __restrict__ maskp,
    __half* __restrict__ Ohg, __half* __restrict__ Olg)
{
    extern __shared__ __align__(128) char sm[];
    const uint32_t sb = smem_u32(sm);
    float* S = (float*)(sm + AT_SS);

    const int h  = blockIdx.x;
    const int nb = blockIdx.y;
    const int b  = blockIdx.z;
    const int tid = threadIdx.x, wid = tid >> 5, lane = tid & 31;
    const int g = lane >> 3, r = lane & 7;
    const size_t bn = (size_t)b * NBL + nb;

    // ---- load Q (64x64) and K/V (65x64 + zero pad to 80 rows) ----
    for (int i = tid; i < 512; i += 256) {
        int row = i >> 3, ch = i & 7;
        size_t go = (bn * 64 + row) * 512 + h * 64 + ch * 8;
        *(uint4*)(sm + AT_QH + row * 144 + ch * 16) = *(const uint4*)&Qhg[go];
        *(uint4*)(sm + AT_QL + row * 144 + ch * 16) = *(const uint4*)&Qlg[go];
    }
    for (int i = tid; i < 640; i += 256) {
        int row = i >> 3, ch = i & 7;
        uint4 kh = {0,0,0,0}, kl = {0,0,0,0}, vh = {0,0,0,0};
        if (row < 65) {
            size_t go = (bn * 65 + row) * 1024 + h * 64 + ch * 8;
            kh = *(const uint4*)&KVhg[go];
            kl = *(const uint4*)&KVlg[go];
            vh = *(const uint4*)&KVhg[go + 512];
        }
        *(uint4*)(sm + AT_KH + row * 144 + ch * 16) = kh;
        *(uint4*)(sm + AT_KL + row * 144 + ch * 16) = kl;
        *(uint4*)(sm + AT_VH + row * 144 + ch * 16) = vh;
    }
    __syncthreads();

    // ---- scores: S[64][80] = Q @ K^T (3-product) ----
    const int warp_m = wid & 3, warp_n = wid >> 2;
    const int m0 = warp_m * 16, n0 = warp_n * 48;
    const int ntc = warp_n ? 2 : 3;
    {
        float sacc[3][8];
#pragma unroll
        for (int t = 0; t < 3; t++)
#pragma unroll
            for (int q = 0; q < 8; q++) sacc[t][q] = 0.f;

#pragma unroll
        for (int ks = 0; ks < 4; ks++) {
            uint32_t qh4[4], ql4[4], kh4[3][4], kl4[3][4];
            uint32_t qa = sb + AT_QH + (m0 + (g & 1) * 8 + r) * 144 + (g >> 1) * 16 + ks * 32;
            LDSM4(qh4, qa);
            LDSM4(ql4, qa + (AT_QL - AT_QH));
#pragma unroll
            for (int t = 0; t < 3; t++) {
                if (t < ntc) {
                    uint32_t ka = sb + AT_KH + (n0 + t * 16 + (g & 1) * 8 + r) * 144
                                  + (g >> 1) * 16 + ks * 32;
                    LDSM4(kh4[t], ka);
                    LDSM4(kl4[t], ka + (AT_KL - AT_KH));
                }
            }
#pragma unroll
            for (int t = 0; t < 3; t++) {
                if (t < ntc) {
#pragma unroll
                    for (int o = 0; o < 2; o++) {
                        uint32_t bfh[2] = { kh4[t][o], kh4[t][o + 2] };
                        uint32_t bfl[2] = { kl4[t][o], kl4[t][o + 2] };
                        MMA16816F16(sacc[t] + o * 4, qh4, bfh);
                        MMA16816F16(sacc[t] + o * 4, ql4, bfh);
                        MMA16816F16(sacc[t] + o * 4, qh4, bfl);
                    }
                }
            }
        }
#pragma unroll
        for (int t = 0; t < 3; t++) {
            if (t < ntc) {
#pragma unroll
                for (int o = 0; o < 2; o++) {
                    int col = n0 + t * 16 + o * 8 + (lane & 3) * 2;
                    int row = m0 + (lane >> 2);
                    *(float2*)&S[row * 100 + col] =
                        make_float2(sacc[t][o * 4], sacc[t][o * 4 + 1]);
                    *(float2*)&S[(row + 8) * 100 + col] =
                        make_float2(sacc[t][o * 4 + 2], sacc[t][o * 4 + 3]);
                }
            }
        }
    }
    __syncthreads();

    // ---- scale + bias + mask (cols < 65) ----
    const int mode = g_mask_mode;
    for (int idx = tid; idx < 64 * 65; idx += 256) {
        int l  = idx / 65;
        int kk = idx - l * 65;
        float s = S[l * 100 + kk] * SCALE;
        float bias;
        if (kk == 64 || kk == l) bias = 1.0f;
        else bias = edge[((((size_t)nb * 64) + l) * 65 + kk) * 4 + 3];
        s += bias;
        size_t mi = ((size_t)nb * 64 + l) * 65 + kk;
        bool ok;
        if (mode == 0)      ok = ((const unsigned char*)maskp)[mi] != 0;
        else if (mode == 1) ok = ((const int*)maskp)[mi] != 0;
        else                ok = ((const float*)maskp)[mi] != 0.0f;
        S[l * 100 + kk] = ok ? s : -1.0e9f;
    }
    __syncthreads();

    // ---- softmax (no max-shift; 1 expf/elem) + fused A fp16 conversion ----
    for (int rr = wid; rr < 64; rr += 8) {
        float sum = 0.f;
        for (int kk = lane; kk < 65; kk += 32) {
            float e = __expf(S[rr * 100 + kk]);   // -1e9 -> 0.0f
            S[rr * 100 + kk] = e;
            sum += e;
        }
#pragma unroll
        for (int off = 16; off; off >>= 1) sum += __shfl_xor_sync(0xffffffffu, sum, off);
        float inv = 1.0f / sum;
        for (int kk = lane; kk < 80; kk += 32) {
            float v = (kk < 65) ? S[rr * 100 + kk] * inv : 0.f;
            *(__half*)(sm + AT_AH + (rr * 104 + kk) * 2) = __float2half(v);
        }
    }
    __syncthreads();

    // ---- O = A @ V (1-product) ----
    {
        const int n0w = warp_n * 32;
        float oacc[4][4];
#pragma unroll
        for (int na = 0; na < 4; na++)
#pragma unroll
            for (int q = 0; q < 4; q++) oacc[na][q] = 0.f;

#pragma unroll
        for (int ks = 0; ks < 5; ks++) {
            uint32_t ah4[4], vh4[2][4];
            uint32_t aa = sb + AT_AH + (m0 + (g & 1) * 8 + r) * 208 + (g >> 1) * 16 + ks * 32;
            LDSM4(ah4, aa);
#pragma unroll
            for (int p = 0; p < 2; p++) {
                uint32_t va = sb + AT_VH + (ks * 16 + (g & 1) * 8 + r) * 144
                              + (n0w + (g >> 1) * 8) * 2 + p * 32;
                LDSM4T(vh4[p], va);
            }
#pragma unroll
            for (int na = 0; na < 4; na++) {
                int p = na >> 1, q = (na & 1) * 2;
                MMA16816F16(oacc[na], ah4, vh4[p] + q);
            }
        }
#pragma unroll
        for (int na = 0; na < 4; na++) {
            int d = n0w + na * 8 + (lane & 3) * 2;
            int l = m0 + (lane >> 2);
            size_t o0 = (bn * 64 + l) * 512 + h * 64 + d;
            size_t o1 = (bn * 64 + l + 8) * 512 + h * 64 + d;
            float v0 = oacc[na][0], v1 = oacc[na][1];
            float v2 = oacc[na][2], v3 = oacc[na][3];
            __half h0 = __float2half(v0), h1 = __float2half(v1);
            __half h2 = __float2half(v2), h3 = __float2half(v3);
            *(__half2*)&Ohg[o0] = __halves2half2(h0, h1);
            *(__half2*)&Ohg[o1] = __halves2half2(h2, h3);
            *(__half2*)&Olg[o0] = __halves2half2(__float2half(v0 - __half2float(h0)),
                                                 __float2half(v1 - __half2float(h1)));
            *(__half2*)&Olg[o1] = __halves2half2(__float2half(v2 - __half2float(h2)),
                                                 __float2half(v3 - __half2float(h3)));
        }
    }
}

// ================= launch =================
extern "C" void kernel_launch(void* const* d_in, const int* in_sizes, int n_in,
                              void* d_out, int out_size) {
    const float *x = 0, *edge = 0, *qkv_w = 0, *qkv_b = 0, *proj_w = 0, *proj_b = 0;
    const void  *mask = 0;
    for (int i = 0; i < n_in; i++) {
        switch (in_sizes[i]) {
            case 33554432: x      = (const float*)d_in[i]; break;
            case 1064960:  mask   = d_in[i];               break;
            case 4259840:  edge   = (const float*)d_in[i]; break;
            case 786432:   qkv_w  = (const float*)d_in[i]; break;
            case 1536:     qkv_b  = (const float*)d_in[i]; break;
            case 262144:   proj_w = (const float*)d_in[i]; break;
            case 512:      proj_b = (const float*)d_in[i]; break;
            default: break;
        }
    }
    float* out = (float*)d_out;

    __half *xh, *xl, *bmh, *bml, *wqh, *wph, *Qh, *Ql, *KVh, *KVl, *Oh, *Ol;
    cudaGetSymbolAddress((void**)&xh, g_xh);
    cudaGetSymbolAddress((void**)&xl, g_xl);
    cudaGetSymbolAddress((void**)&bmh, g_bmh);
    cudaGetSymbolAddress((void**)&bml, g_bml);
    cudaGetSymbolAddress((void**)&wqh, g_wqh);
    cudaGetSymbolAddress((void**)&wph, g_wph);
    cudaGetSymbolAddress((void**)&Qh, g_Qh);
    cudaGetSymbolAddress((void**)&Ql, g_Ql);
    cudaGetSymbolAddress((void**)&KVh, g_KVh);
    cudaGetSymbolAddress((void**)&KVl, g_KVl);
    cudaGetSymbolAddress((void**)&Oh, g_Oh);
    cudaGetSymbolAddress((void**)&Ol, g_Ol);

    cudaFuncSetAttribute(gemm_mma, cudaFuncAttributeMaxDynamicSharedMemorySize, GEMM_SMEM);
    cudaFuncSetAttribute(attn_mma, cudaFuncAttributeMaxDynamicSharedMemorySize, AT_SMEM);

    // 1. x -> fp16 hi/lo
    {
        size_t n = (size_t)BB * NBL * LQ * CC;
        split_kernel<<<(unsigned)((n + 255) / 256), 256>>>(x, xh, xl, n);
    }
    // 2. block means -> fp16 hi/lo
    block_mean_kernel<<<BB * NBL, CC>>>(x, bmh, bml);
    // 3. both weights -> fp16
    cvt_weights_kernel<<<(786432 + 262144 + 255) / 256, 256>>>(qkv_w, proj_w, wqh, wph);

    // 4. merged QKV GEMM -> Qh/Ql + KVh/KVl (fp16 hi/lo)
    gemm_mma<<<dim3(THREE_C / 128, 66560 / 128), 256, GEMM_SMEM>>>(
        xh, xl, bmh, bml, 1, wqh, THREE_C, qkv_b, 1, nullptr, 0, Qh, Ql, KVh, KVl);

    // 5. mask dtype detection
    detect_mask_kernel<<<1, 256>>>((const unsigned char*)mask);

    // 6. tensor-core attention -> Oh/Ol
    attn_mma<<<dim3(HH, NBL, BB), 256, AT_SMEM>>>(
        Qh, Ql, KVh, KVl, edge, mask, Oh, Ol);

    // 7. out = O @ Wp + bp
    gemm_mma<<<dim3(CC / 128, 65536 / 128), 256, GEMM_SMEM>>>(
        Oh, Ol, bmh, bml, 0, wph, CC, proj_b, 0, out, CC,
        nullptr, nullptr, nullptr, nullptr);
}

// round 17
// speedup vs baseline: 2.3639x; 1.1131x over previous
#include <cuda_runtime.h>
#include <cuda_bf16.h>
#include <cuda_fp16.h>
#include <cstdint>
#include <cstddef>

// Problem constants
#define BB   4
#define NBL  256
#define LQ   64
#define KK_  65
#define CC   512
#define HH   8
#define SCALE 0.125f
#define THREE_C 1536

// ---------------- scratch (static device globals: allocation-free) ----------------
__device__ __align__(128) __half g_xh[(size_t)BB * NBL * LQ * CC];
__device__ __align__(128) __half g_xl[(size_t)BB * NBL * LQ * CC];
__device__ __align__(128) __half g_bmh[(size_t)BB * NBL * CC];
__device__ __align__(128) __half g_bml[(size_t)BB * NBL * CC];
__device__ __align__(128) __half g_wqh[(size_t)CC * THREE_C];
__device__ __align__(128) __half g_wph[(size_t)CC * CC];
__device__ __align__(128) __half g_Qh[(size_t)BB * NBL * LQ * CC];
__device__ __align__(128) __half g_Ql[(size_t)BB * NBL * LQ * CC];
__device__ __align__(128) __half g_KVh[(size_t)BB * NBL * KK_ * 2 * CC];
__device__ __align__(128) __half g_KVl[(size_t)BB * NBL * KK_ * 2 * CC];
__device__ __align__(128) __half g_Oh[(size_t)BB * NBL * LQ * CC];
__device__ int g_mask_mode;

// ================= PTX helpers =================
__device__ __forceinline__ uint32_t smem_u32(const void* p) {
    uint32_t a;
    asm("{ .reg .u64 t; cvta.to.shared.u64 t, %1; cvt.u32.u64 %0, t; }" : "=r"(a) : "l"(p));
    return a;
}
#define CP16(d, s)   asm volatile("cp.async.cg.shared.global [%0], [%1], 16;" :: "r"(d), "l"(s))
#define CP_COMMIT()  asm volatile("cp.async.commit_group;" ::: "memory")
#define CP_WAIT2()   asm volatile("cp.async.wait_group 2;" ::: "memory")

#define LDSM4(d, addr)                                                           \
    asm volatile("ldmatrix.sync.aligned.m8n8.x4.shared.b16 {%0,%1,%2,%3}, [%4];" \
        : "=r"((d)[0]), "=r"((d)[1]), "=r"((d)[2]), "=r"((d)[3]) : "r"(addr))
#define LDSM4T(d, addr)                                                          \
    asm volatile("ldmatrix.sync.aligned.m8n8.x4.trans.shared.b16 {%0,%1,%2,%3}, [%4];" \
        : "=r"((d)[0]), "=r"((d)[1]), "=r"((d)[2]), "=r"((d)[3]) : "r"(addr))

#define MMA16816F16(acc, a, b)                                                   \
    asm volatile("mma.sync.aligned.m16n8k16.row.col.f32.f16.f16.f32 "            \
        "{%0,%1,%2,%3}, {%4,%5,%6,%7}, {%8,%9}, {%0,%1,%2,%3};"                  \
        : "+f"((acc)[0]), "+f"((acc)[1]), "+f"((acc)[2]), "+f"((acc)[3])         \
        : "r"((a)[0]), "r"((a)[1]), "r"((a)[2]), "r"((a)[3]),                    \
          "r"((b)[0]), "r"((b)[1]))

// ================= small kernels =================
__global__ void detect_mask_kernel(const unsigned char* __restrict__ m) {
    __shared__ int sA, s0;
    if (threadIdx.x == 0) { sA = 0; s0 = 0; }
    __syncthreads();
    int a = 0, z = 0;
    for (int i = threadIdx.x; i < 4096; i += blockDim.x) {
        int v = m[i];
        if ((i & 3) == 1) a |= v;
        if ((i & 3) == 0) z |= v;
    }
    if (a) atomicOr(&sA, 1);
    if (z) atomicOr(&s0, 1);
    __syncthreads();
    if (threadIdx.x == 0) g_mask_mode = sA ? 0 : (s0 ? 1 : 2);
}

// Fused: x -> fp16 hi/lo AND per-block column means -> fp16 hi/lo (one x read)
__global__ void split_mean_kernel(const float* __restrict__ x,
                                  __half* __restrict__ xh, __half* __restrict__ xl,
                                  __half* __restrict__ bmh, __half* __restrict__ bml) {
    int blk = blockIdx.x, c = threadIdx.x;   // 512 threads
    size_t base = (size_t)blk * LQ * CC + c;
    float s = 0.f;
#pragma unroll
    for (int l = 0; l < LQ; l++) {
        float v = x[base + (size_t)l * CC];
        s += v;
        __half h = __float2half(v);
        xh[base + (size_t)l * CC] = h;
        xl[base + (size_t)l * CC] = __float2half(v - __half2float(h));
    }
    float m = s * (1.0f / 64.0f);
    __half h = __float2half(m);
    bmh[(size_t)blk * CC + c] = h;
    bml[(size_t)blk * CC + c] = __float2half(m - __half2float(h));
}

__global__ void cvt_weights_kernel(const float* __restrict__ wq,
                                   const float* __restrict__ wp,
                                   __half* __restrict__ wqh, __half* __restrict__ wph) {
    size_t i = (size_t)blockIdx.x * blockDim.x + threadIdx.x;
    const size_t n1 = (size_t)CC * THREE_C;
    const size_t n2 = (size_t)CC * CC;
    if (i < n1) wqh[i] = __float2half(wq[i]);
    else if (i < n1 + n2) wph[i - n1] = __float2half(wp[i - n1]);
}

// ================= mma.sync fp16 GEMM (templated product count) =================
#define KCHUNK     32
#define NCHUNK     16
#define A_STRIDE_B 80
#define B_STRIDE_B 272
#define A_HALF     10240
#define B_OFF      20480
#define STAGE_BYTES 29184
#define GEMM_SMEM  (3 * STAGE_BYTES)

__device__ __forceinline__ void a_ptrs(
    const __half* __restrict__ Ah, const __half* __restrict__ Al,
    const __half* __restrict__ bmh, const __half* __restrict__ bml,
    int gmode, int gr,
    const __half*& ph, const __half*& pl)
{
    if (gmode == 0) { size_t o = (size_t)gr * CC; ph = Ah + o; pl = Al + o; return; }
    int b  = gr / (NBL * KK_);
    int t  = gr - b * (NBL * KK_);
    int nb = t / KK_;
    int kk = t - nb * KK_;
    if (kk < LQ) { size_t o = ((size_t)(b * NBL + nb) * LQ + kk) * CC; ph = Ah + o; pl = Al + o; }
    else         { size_t o = (size_t)(b * NBL + nb) * CC;             ph = bmh + o; pl = bml + o; }
}

template<int NPROD>
__global__ __launch_bounds__(256) void gemm_mma(
    const __half* __restrict__ Ah, const __half* __restrict__ Al,
    const __half* __restrict__ bmh, const __half* __restrict__ bml,
    int gmode,
    const __half* __restrict__ Bh, int ldB,
    const float* __restrict__ bias,
    int epi_mode,
    float* __restrict__ C, int ldc,
    __half* __restrict__ QhP, __half* __restrict__ QlP,
    __half* __restrict__ KVhP, __half* __restrict__ KVlP)
{
    extern __shared__ __align__(128) char smem[];
    const uint32_t sb = smem_u32(smem);
    const int tid = threadIdx.x, wid = tid >> 5, lane = tid & 31;
    const int warp_m = wid >> 2, warp_n = wid & 3;
    const int rowBase = blockIdx.y * 128;
    const int colBase = blockIdx.x * 128;
    const int g = lane >> 3, r = lane & 7;

    float acc[4][4][4];
#pragma unroll
    for (int ma = 0; ma < 4; ma++)
#pragma unroll
        for (int na = 0; na < 4; na++)
#pragma unroll
            for (int q = 0; q < 4; q++) acc[ma][na][q] = 0.f;

    const uint32_t aOff = (uint32_t)((warp_m * 64 + (g & 1) * 8 + r) * A_STRIDE_B + (g >> 1) * 16);
    const uint32_t bOff = (uint32_t)(B_OFF + ((g & 1) * 8 + r) * B_STRIDE_B
                                     + (warp_n * 32 + (g >> 1) * 8) * 2);

    auto load_chunk = [&](int k0, uint32_t stBase) {
#pragma unroll
        for (int i = tid; i < 512; i += 256) {
            int row = i >> 2, seg = i & 3;
            const __half *ph, *pl;
            a_ptrs(Ah, Al, bmh, bml, gmode, rowBase + row, ph, pl);
            uint32_t da = stBase + row * A_STRIDE_B + seg * 16;
            CP16(da, ph + k0 + seg * 8);
            if (NPROD == 2) CP16(da + A_HALF, pl + k0 + seg * 8);
        }
#pragma unroll
        for (int i = tid; i < 512; i += 256) {
            int row = i >> 4, seg = i & 15;
            size_t off = (size_t)(k0 + row) * ldB + colBase + seg * 8;
            CP16(stBase + B_OFF + row * B_STRIDE_B + seg * 16, Bh + off);
        }
    };

#pragma unroll
    for (int s = 0; s < 3; s++) {
        load_chunk(s * KCHUNK, sb + s * STAGE_BYTES);
        CP_COMMIT();
    }

    for (int c = 0; c < NCHUNK; c++) {
        CP_WAIT2();
        __syncthreads();
        const uint32_t st = sb + (c % 3) * STAGE_BYTES;

#pragma unroll
        for (int ks = 0; ks < 2; ks++) {
            uint32_t ah[4][4], al[4][4], bh[2][4];
#pragma unroll
            for (int ma = 0; ma < 4; ma++) {
                uint32_t ad = st + aOff + ma * (16 * A_STRIDE_B) + ks * 32;
                LDSM4(ah[ma], ad);
                if (NPROD == 2) LDSM4(al[ma], ad + A_HALF);
            }
#pragma unroll
            for (int p = 0; p < 2; p++) {
                uint32_t bd = st + bOff + ks * (16 * B_STRIDE_B) + p * 32;
                LDSM4T(bh[p], bd);
            }
#pragma unroll
            for (int ma = 0; ma < 4; ma++)
#pragma unroll
                for (int na = 0; na < 4; na++) {
                    int p = na >> 1, q = (na & 1) * 2;
                    MMA16816F16(acc[ma][na], ah[ma], bh[p] + q);
                    if (NPROD == 2) MMA16816F16(acc[ma][na], al[ma], bh[p] + q);
                }
        }
        __syncthreads();
        if (c + 3 < NCHUNK) load_chunk((c + 3) * KCHUNK, st);
        CP_COMMIT();
    }

    // ---- epilogue ----
    if (epi_mode == 0) {
#pragma unroll
        for (int ma = 0; ma < 4; ma++) {
            int gr = rowBase + warp_m * 64 + ma * 16 + (lane >> 2);
#pragma unroll
            for (int na = 0; na < 4; na++) {
                int gc = colBase + warp_n * 32 + na * 8 + 2 * (lane & 3);
                float b0 = bias[gc], b1 = bias[gc + 1];
                float2 v0 = make_float2(acc[ma][na][0] + b0, acc[ma][na][1] + b1);
                float2 v1 = make_float2(acc[ma][na][2] + b0, acc[ma][na][3] + b1);
                *(float2*)&C[(size_t)gr * ldc + gc]       = v0;
                *(float2*)&C[(size_t)(gr + 8) * ldc + gc] = v1;
            }
        }
    } else {
        const bool isQ = (colBase < 512);
#pragma unroll
        for (int ma = 0; ma < 4; ma++) {
            int gr0 = rowBase + warp_m * 64 + ma * 16 + (lane >> 2);
#pragma unroll
            for (int rr = 0; rr < 2; rr++) {
                int gr = gr0 + rr * 8;
                int b  = gr / (NBL * KK_);
                int t  = gr - b * (NBL * KK_);
                int nb = t / KK_;
                int kk = t - nb * KK_;
                size_t bn = (size_t)b * NBL + nb;
                __half *dh, *dl;
                int cshift;
                if (isQ) {
                    if (kk >= LQ) continue;
                    size_t o = (bn * 64 + kk) * 512;
                    dh = QhP + o; dl = QlP + o; cshift = 0;
                } else {
                    size_t o = (bn * 65 + kk) * 1024;
                    dh = KVhP + o; dl = KVlP + o; cshift = 512;
                }
#pragma unroll
                for (int na = 0; na < 4; na++) {
                    int gc = colBase + warp_n * 32 + na * 8 + 2 * (lane & 3);
                    float v0 = acc[ma][na][rr * 2]     + bias[gc];
                    float v1 = acc[ma][na][rr * 2 + 1] + bias[gc + 1];
                    __half h0 = __float2half(v0), h1 = __float2half(v1);
                    __half l0 = __float2half(v0 - __half2float(h0));
                    __half l1 = __float2half(v1 - __half2float(h1));
                    int cc = gc - cshift;
                    *(__half2*)&dh[cc] = __halves2half2(h0, h1);
                    *(__half2*)&dl[cc] = __halves2half2(l0, l1);
                }
            }
        }
    }
}

// ================= mma.sync attention per (b,nb,h) ==========================
// K padded to 80 rows. Scores 3-product; AV 1-product; O written hi-only
// (proj GEMM is 1-product and needs no lo residual).
#define AT_QH 0
#define AT_QL 9216
#define AT_KH 18432
#define AT_KL 29952
#define AT_VH 41472
#define AT_SS 52992
#define AT_AH 78592
#define AT_SMEM 91904

__global__ __launch_bounds__(256) void attn_mma(
    const __half* __restrict__ Qhg, const __half* __restrict__ Qlg,
    const __half* __restrict__ KVhg, const __half* __restrict__ KVlg,
    const float* __restrict__ edge, const void* __restrict__ maskp,
    __half* __restrict__ Ohg)
{
    extern __shared__ __align__(128) char sm[];
    const uint32_t sb = smem_u32(sm);
    float* S = (float*)(sm + AT_SS);

    const int h  = blockIdx.x;
    const int nb = blockIdx.y;
    const int b  = blockIdx.z;
    const int tid = threadIdx.x, wid = tid >> 5, lane = tid & 31;
    const int g = lane >> 3, r = lane & 7;
    const size_t bn = (size_t)b * NBL + nb;

    for (int i = tid; i < 512; i += 256) {
        int row = i >> 3, ch = i & 7;
        size_t go = (bn * 64 + row) * 512 + h * 64 + ch * 8;
        *(uint4*)(sm + AT_QH + row * 144 + ch * 16) = *(const uint4*)&Qhg[go];
        *(uint4*)(sm + AT_QL + row * 144 + ch * 16) = *(const uint4*)&Qlg[go];
    }
    for (int i = tid; i < 640; i += 256) {
        int row = i >> 3, ch = i & 7;
        uint4 kh = {0,0,0,0}, kl = {0,0,0,0}, vh = {0,0,0,0};
        if (row < 65) {
            size_t go = (bn * 65 + row) * 1024 + h * 64 + ch * 8;
            kh = *(const uint4*)&KVhg[go];
            kl = *(const uint4*)&KVlg[go];
            vh = *(const uint4*)&KVhg[go + 512];
        }
        *(uint4*)(sm + AT_KH + row * 144 + ch * 16) = kh;
        *(uint4*)(sm + AT_KL + row * 144 + ch * 16) = kl;
        *(uint4*)(sm + AT_VH + row * 144 + ch * 16) = vh;
    }
    __syncthreads();

    // ---- scores: S[64][80] = Q @ K^T (3-product) ----
    const int warp_m = wid & 3, warp_n = wid >> 2;
    const int m0 = warp_m * 16, n0 = warp_n * 48;
    const int ntc = warp_n ? 2 : 3;
    {
        float sacc[3][8];
#pragma unroll
        for (int t = 0; t < 3; t++)
#pragma unroll
            for (int q = 0; q < 8; q++) sacc[t][q] = 0.f;

#pragma unroll
        for (int ks = 0; ks < 4; ks++) {
            uint32_t qh4[4], ql4[4], kh4[3][4], kl4[3][4];
            uint32_t qa = sb + AT_QH + (m0 + (g & 1) * 8 + r) * 144 + (g >> 1) * 16 + ks * 32;
            LDSM4(qh4, qa);
            LDSM4(ql4, qa + (AT_QL - AT_QH));
#pragma unroll
            for (int t = 0; t < 3; t++) {
                if (t < ntc) {
                    uint32_t ka = sb + AT_KH + (n0 + t * 16 + (g & 1) * 8 + r) * 144
                                  + (g >> 1) * 16 + ks * 32;
                    LDSM4(kh4[t], ka);
                    LDSM4(kl4[t], ka + (AT_KL - AT_KH));
                }
            }
#pragma unroll
            for (int t = 0; t < 3; t++) {
                if (t < ntc) {
#pragma unroll
                    for (int o = 0; o < 2; o++) {
                        uint32_t bfh[2] = { kh4[t][o], kh4[t][o + 2] };
                        uint32_t bfl[2] = { kl4[t][o], kl4[t][o + 2] };
                        MMA16816F16(sacc[t] + o * 4, qh4, bfh);
                        MMA16816F16(sacc[t] + o * 4, ql4, bfh);
                        MMA16816F16(sacc[t] + o * 4, qh4, bfl);
                    }
                }
            }
        }
#pragma unroll
        for (int t = 0; t < 3; t++) {
            if (t < ntc) {
#pragma unroll
                for (int o = 0; o < 2; o++) {
                    int col = n0 + t * 16 + o * 8 + (lane & 3) * 2;
                    int row = m0 + (lane >> 2);
                    *(float2*)&S[row * 100 + col] =
                        make_float2(sacc[t][o * 4], sacc[t][o * 4 + 1]);
                    *(float2*)&S[(row + 8) * 100 + col] =
                        make_float2(sacc[t][o * 4 + 2], sacc[t][o * 4 + 3]);
                }
            }
        }
    }
    __syncthreads();

    // ---- scale + bias + mask (cols < 65) ----
    const int mode = g_mask_mode;
    for (int idx = tid; idx < 64 * 65; idx += 256) {
        int l  = idx / 65;
        int kk = idx - l * 65;
        float s = S[l * 100 + kk] * SCALE;
        float bias;
        if (kk == 64 || kk == l) bias = 1.0f;
        else bias = edge[((((size_t)nb * 64) + l) * 65 + kk) * 4 + 3];
        s += bias;
        size_t mi = ((size_t)nb * 64 + l) * 65 + kk;
        bool ok;
        if (mode == 0)      ok = ((const unsigned char*)maskp)[mi] != 0;
        else if (mode == 1) ok = ((const int*)maskp)[mi] != 0;
        else                ok = ((const float*)maskp)[mi] != 0.0f;
        S[l * 100 + kk] = ok ? s : -1.0e9f;
    }
    __syncthreads();

    // ---- softmax (no max-shift; 1 expf/elem) + fused A fp16 conversion ----
    for (int rr = wid; rr < 64; rr += 8) {
        float sum = 0.f;
        for (int kk = lane; kk < 65; kk += 32) {
            float e = __expf(S[rr * 100 + kk]);
            S[rr * 100 + kk] = e;
            sum += e;
        }
#pragma unroll
        for (int off = 16; off; off >>= 1) sum += __shfl_xor_sync(0xffffffffu, sum, off);
        float inv = 1.0f / sum;
        for (int kk = lane; kk < 80; kk += 32) {
            float v = (kk < 65) ? S[rr * 100 + kk] * inv : 0.f;
            *(__half*)(sm + AT_AH + (rr * 104 + kk) * 2) = __float2half(v);
        }
    }
    __syncthreads();

    // ---- O = A @ V (1-product), write hi only ----
    {
        const int n0w = warp_n * 32;
        float oacc[4][4];
#pragma unroll
        for (int na = 0; na < 4; na++)
#pragma unroll
            for (int q = 0; q < 4; q++) oacc[na][q] = 0.f;

#pragma unroll
        for (int ks = 0; ks < 5; ks++) {
            uint32_t ah4[4], vh4[2][4];
            uint32_t aa = sb + AT_AH + (m0 + (g & 1) * 8 + r) * 208 + (g >> 1) * 16 + ks * 32;
            LDSM4(ah4, aa);
#pragma unroll
            for (int p = 0; p < 2; p++) {
                uint32_t va = sb + AT_VH + (ks * 16 + (g & 1) * 8 + r) * 144
                              + (n0w + (g >> 1) * 8) * 2 + p * 32;
                LDSM4T(vh4[p], va);
            }
#pragma unroll
            for (int na = 0; na < 4; na++) {
                int p = na >> 1, q = (na & 1) * 2;
                MMA16816F16(oacc[na], ah4, vh4[p] + q);
            }
        }
#pragma unroll
        for (int na = 0; na < 4; na++) {
            int d = n0w + na * 8 + (lane & 3) * 2;
            int l = m0 + (lane >> 2);
            size_t o0 = (bn * 64 + l) * 512 + h * 64 + d;
            size_t o1 = (bn * 64 + l + 8) * 512 + h * 64 + d;
            *(__half2*)&Ohg[o0] = __halves2half2(__float2half(oacc[na][0]),
                                                 __float2half(oacc[na][1]));
            *(__half2*)&Ohg[o1] = __halves2half2(__float2half(oacc[na][2]),
                                                 __float2half(oacc[na][3]));
        }
    }
}

// ================= launch =================
extern "C" void kernel_launch(void* const* d_in, const int* in_sizes, int n_in,
                              void* d_out, int out_size) {
    const float *x = 0, *edge = 0, *qkv_w = 0, *qkv_b = 0, *proj_w = 0, *proj_b = 0;
    const void  *mask = 0;
    for (int i = 0; i < n_in; i++) {
        switch (in_sizes[i]) {
            case 33554432: x      = (const float*)d_in[i]; break;
            case 1064960:  mask   = d_in[i];               break;
            case 4259840:  edge   = (const float*)d_in[i]; break;
            case 786432:   qkv_w  = (const float*)d_in[i]; break;
            case 1536:     qkv_b  = (const float*)d_in[i]; break;
            case 262144:   proj_w = (const float*)d_in[i]; break;
            case 512:      proj_b = (const float*)d_in[i]; break;
            default: break;
        }
    }
    float* out = (float*)d_out;

    __half *xh, *xl, *bmh, *bml, *wqh, *wph, *Qh, *Ql, *KVh, *KVl, *Oh;
    cudaGetSymbolAddress((void**)&xh, g_xh);
    cudaGetSymbolAddress((void**)&xl, g_xl);
    cudaGetSymbolAddress((void**)&bmh, g_bmh);
    cudaGetSymbolAddress((void**)&bml, g_bml);
    cudaGetSymbolAddress((void**)&wqh, g_wqh);
    cudaGetSymbolAddress((void**)&wph, g_wph);
    cudaGetSymbolAddress((void**)&Qh, g_Qh);
    cudaGetSymbolAddress((void**)&Ql, g_Ql);
    cudaGetSymbolAddress((void**)&KVh, g_KVh);
    cudaGetSymbolAddress((void**)&KVl, g_KVl);
    cudaGetSymbolAddress((void**)&Oh, g_Oh);

    cudaFuncSetAttribute(gemm_mma<2>, cudaFuncAttributeMaxDynamicSharedMemorySize, GEMM_SMEM);
    cudaFuncSetAttribute(gemm_mma<1>, cudaFuncAttributeMaxDynamicSharedMemorySize, GEMM_SMEM);
    cudaFuncSetAttribute(attn_mma, cudaFuncAttributeMaxDynamicSharedMemorySize, AT_SMEM);

    // 1. fused: x -> fp16 hi/lo + block means
    split_mean_kernel<<<BB * NBL, CC>>>(x, xh, xl, bmh, bml);
    // 2. both weights -> fp16
    cvt_weights_kernel<<<(786432 + 262144 + 255) / 256, 256>>>(qkv_w, proj_w, wqh, wph);
    // 3. mask dtype detection
    detect_mask_kernel<<<1, 256>>>((const unsigned char*)mask);

    // 4. merged QKV GEMM (2-product) -> Qh/Ql + KVh/KVl
    gemm_mma<2><<<dim3(THREE_C / 128, 66560 / 128), 256, GEMM_SMEM>>>(
        xh, xl, bmh, bml, 1, wqh, THREE_C, qkv_b, 1, nullptr, 0, Qh, Ql, KVh, KVl);

    // 5. tensor-core attention -> Oh (hi only)
    attn_mma<<<dim3(HH, NBL, BB), 256, AT_SMEM>>>(
        Qh, Ql, KVh, KVl, edge, mask, Oh);

    // 6. out = Oh @ Wp + bp (1-product)
    gemm_mma<1><<<dim3(CC / 128, 65536 / 128), 256, GEMM_SMEM>>>(
        Oh, Oh, bmh, bml, 0, wph, CC, proj_b, 0, out, CC,
        nullptr, nullptr, nullptr, nullptr);
}